// round 9
// baseline (speedup 1.0000x reference)
#include <cuda_runtime.h>

// SpatialAttention: per-node fused QKV proj + attention (softmax over QUERY axis) + out proj.
// Round 9: NT=256 / 12-rows-per-warp register tiles, swizzled conflict-free W staging,
// float4-broadcast A reads in A*V, STS.128 S-writes. FFMA2 everywhere (bit-exact fp32).

#define TT 96
#define CCH 128
#define NH 4
#define HDIM 32
#define LDA 132      // padded row stride (floats) for x/Q/K/V
#define LDSS 100     // S_T row stride (floats)
#define LDW 128      // W slab row stride (swizzled)
#define NT 256
#define ROWS 12      // q-rows per warp (8 warps * 12 = 96)

// shared-memory float offsets
#define OFF_X 0                    // x: 96*132 = 12672   (region A)
#define OFF_S 0                    // S_T: 96*100 = 9600  (reuses region A after QKV)
#define OFF_O 9600                 // O_h: 96*32  = 3072
#define OFF_Q 12672                // 96*132
#define OFF_K 25344
#define OFF_V 38016
#define OFF_W 50688                // W slab: 32*128 = 4096 (XOR-swizzled)
#define SMEM_FLOATS (50688 + 4096) // 54784 floats = 219136 B
#define SMEM_BYTES (SMEM_FLOATS * 4)

// swizzle: row c (0..31) stores col j at j ^ (c & 28)  -> conflict-free STS + LDS
#define SWZ(c, j) ((j) ^ ((c) & 28))

typedef unsigned long long u64x;

#define FMA2(d, a, b) \
    asm("fma.rn.f32x2 %0, %1, %2, %0;" : "+l"(d) : "l"(a), "l"(b))
#define ADD2(d, a, b) \
    asm("add.rn.f32x2 %0, %1, %2;" : "=l"(d) : "l"(a), "l"(b))
#define PKDUP(d, v) do { unsigned _u = __float_as_uint(v); \
    asm("mov.b64 %0, {%1, %1};" : "=l"(d) : "r"(_u)); } while (0)
#define PK(d, xlo, xhi) \
    asm("mov.b64 %0, {%1, %2};" : "=l"(d) : "r"(__float_as_uint(xlo)), "r"(__float_as_uint(xhi)))
#define UNPK(xlo, xhi, d) do { unsigned _l, _h; \
    asm("mov.b64 {%0, %1}, %2;" : "=r"(_l), "=r"(_h) : "l"(d)); \
    xlo = __uint_as_float(_l); xhi = __uint_as_float(_h); } while (0)

// Stage W[j][c0..c0+31] (row-major 128x128) into sm[OFF_W] as Ws[c_local][j^swz].
// NT=256: t -> ccg = t&7 (4-col chunk of c), jr = t>>3 (0..31), 4 reps over j.
__device__ __forceinline__ void stage_w32(float* sm, const float* __restrict__ W, int c0, int t)
{
    const int ccg = t & 7;
    const int jr  = t >> 3;
#pragma unroll
    for (int rep = 0; rep < 4; ++rep) {
        const int j = jr + rep * 32;
        float4 w = *(const float4*)(W + j * CCH + c0 + ccg * 4);
        const int r0 = ccg * 4;
        sm[OFF_W + (r0 + 0) * LDW + SWZ(r0 + 0, j)] = w.x;
        sm[OFF_W + (r0 + 1) * LDW + SWZ(r0 + 1, j)] = w.y;
        sm[OFF_W + (r0 + 2) * LDW + SWZ(r0 + 2, j)] = w.z;
        sm[OFF_W + (r0 + 3) * LDW + SWZ(r0 + 3, j)] = w.w;
    }
}

__global__ __launch_bounds__(NT, 1)
void spatial_attn_kernel(const float* __restrict__ x,
                         const float* __restrict__ Wq, const float* __restrict__ bq,
                         const float* __restrict__ Wk, const float* __restrict__ bk,
                         const float* __restrict__ Wv, const float* __restrict__ bv,
                         const float* __restrict__ Wo, const float* __restrict__ bo,
                         float* __restrict__ out)
{
    extern __shared__ float sm[];
    const int t    = threadIdx.x;
    const int lane = t & 31;
    const int qg   = t >> 5;         // warp id, 0..7
    const int q0   = qg * ROWS;      // this warp's 12 query rows
    const size_t gbase = (size_t)blockIdx.x * (TT * CCH);
    const float* xg = x + gbase;
    float* yg = out + gbase;

    // ---- phase 1: load x (96x128) into padded SMEM ----
    {
        const float4* xv = (const float4*)xg;   // 3072 float4
#pragma unroll
        for (int it = 0; it < 12; ++it) {
            const int e  = it * NT + t;
            const int q  = e >> 5;
            const int c4 = e & 31;
            float4 v = xv[e];
            *(float4*)(sm + OFF_X + q * LDA + c4 * 4) = v;
        }
    }
    __syncthreads();

    // ---- phase 2: Q/K/V = x @ W^T + b  (FFMA2, 12x4 register tile) ----
    {
        const float* Wm[3]   = {Wq, Wk, Wv};
        const float* bm[3]   = {bq, bk, bv};
        const int    offp[3] = {OFF_Q, OFF_K, OFF_V};
        const int jb = lane * 4;
#pragma unroll 1
        for (int m = 0; m < 3; ++m) {
            u64x acc2[ROWS][2];
#pragma unroll
            for (int i = 0; i < ROWS; ++i) { acc2[i][0] = 0ull; acc2[i][1] = 0ull; }
            const float* W = Wm[m];
#pragma unroll 1
            for (int s = 0; s < 4; ++s) {
                const int c0 = s * 32;
                __syncthreads();
                stage_w32(sm, W, c0, t);
                __syncthreads();
#pragma unroll
                for (int c4 = 0; c4 < 8; ++c4) {
                    float4 xr[ROWS];
#pragma unroll
                    for (int i = 0; i < ROWS; ++i)
                        xr[i] = *(const float4*)(sm + OFF_X + (q0 + i) * LDA + c0 + c4 * 4);
#pragma unroll
                    for (int cc = 0; cc < 4; ++cc) {
                        const int cl = c4 * 4 + cc;
                        ulonglong2 w2 = *(const ulonglong2*)(sm + OFF_W + cl * LDW + SWZ(cl, jb));
#pragma unroll
                        for (int i = 0; i < ROWS; ++i) {
                            const float xvv = ((const float*)&xr[i])[cc];
                            u64x xp; PKDUP(xp, xvv);
                            FMA2(acc2[i][0], xp, w2.x);
                            FMA2(acc2[i][1], xp, w2.y);
                        }
                    }
                }
            }
            const float4 b4 = *(const float4*)(bm[m] + jb);
            u64x b01, b23; PK(b01, b4.x, b4.y); PK(b23, b4.z, b4.w);
            const int off = offp[m];
#pragma unroll
            for (int i = 0; i < ROWS; ++i) {
                ulonglong2 r2;
                ADD2(r2.x, acc2[i][0], b01);
                ADD2(r2.y, acc2[i][1], b23);
                *(ulonglong2*)(sm + off + (q0 + i) * LDA + jb) = r2;
            }
        }
    }
    __syncthreads();   // Q/K/V ready; x region free

    // ---- phases 3-6 per head ----
    const float scale = 0.17677669529663687f;  // 1/sqrt(32)
    u64x accy2[ROWS][2];
#pragma unroll
    for (int i = 0; i < ROWS; ++i) { accy2[i][0] = 0ull; accy2[i][1] = 0ull; }
    const int jb = lane * 4;

#pragma unroll 1
    for (int h = 0; h < NH; ++h) {
        const int hc = h * HDIM;

        // S_T[k][q] = scale * (Q[q,hc:] . K[k,hc:])  — FFMA2 over reduction dim.
        {
            u64x acc2[ROWS][3];
#pragma unroll
            for (int i = 0; i < ROWS; ++i)
#pragma unroll
                for (int j = 0; j < 3; ++j) acc2[i][j] = 0ull;
            const int kb = lane * 3;
#pragma unroll
            for (int c4 = 0; c4 < 8; ++c4) {
                ulonglong2 qv[ROWS];
#pragma unroll
                for (int i = 0; i < ROWS; ++i)
                    qv[i] = *(const ulonglong2*)(sm + OFF_Q + (q0 + i) * LDA + hc + c4 * 4);
#pragma unroll
                for (int j = 0; j < 3; ++j) {
                    ulonglong2 kv = *(const ulonglong2*)(sm + OFF_K + (kb + j) * LDA + hc + c4 * 4);
#pragma unroll
                    for (int i = 0; i < ROWS; ++i) {
                        FMA2(acc2[i][j], qv[i].x, kv.x);
                        FMA2(acc2[i][j], qv[i].y, kv.y);
                    }
                }
            }
            // write 12 q-values per k-row as 3 STS.128
#pragma unroll
            for (int j = 0; j < 3; ++j) {
                float s[ROWS];
#pragma unroll
                for (int i = 0; i < ROWS; ++i) {
                    float lo, hi; UNPK(lo, hi, acc2[i][j]);
                    s[i] = (lo + hi) * scale;
                }
                float* dst = sm + OFF_S + (kb + j) * LDSS + q0;
#pragma unroll
                for (int b = 0; b < 3; ++b) {
                    float4 v; v.x = s[4*b]; v.y = s[4*b+1]; v.z = s[4*b+2]; v.w = s[4*b+3];
                    *(float4*)(dst + 4 * b) = v;
                }
            }
        }
        __syncthreads();

        // softmax over q (axis=-2): each warp does 12 rows of S_T (row = 96 q's)
        {
#pragma unroll
            for (int r = 0; r < ROWS; ++r) {
                const int k = qg * ROWS + r;
                float v0 = sm[OFF_S + k * LDSS + lane];
                float v1 = sm[OFF_S + k * LDSS + lane + 32];
                float v2 = sm[OFF_S + k * LDSS + lane + 64];
                float mx = fmaxf(v0, fmaxf(v1, v2));
#pragma unroll
                for (int o = 16; o; o >>= 1) mx = fmaxf(mx, __shfl_xor_sync(0xffffffffu, mx, o));
                float e0 = __expf(v0 - mx), e1 = __expf(v1 - mx), e2 = __expf(v2 - mx);
                float s = e0 + e1 + e2;
#pragma unroll
                for (int o = 16; o; o >>= 1) s += __shfl_xor_sync(0xffffffffu, s, o);
                const float inv = 1.f / s;
                sm[OFF_S + k * LDSS + lane]      = e0 * inv;
                sm[OFF_S + k * LDSS + lane + 32] = e1 * inv;
                sm[OFF_S + k * LDSS + lane + 64] = e2 * inv;
            }
        }
        __syncthreads();

        // O[q][d] = sum_k A_T[k][q] * V[k][hc+d]  (d = lane)
        // A reads: 3 float4 broadcasts per k (12 q's); V: one dense 128B row slice.
        {
            u64x acco2[6];
#pragma unroll
            for (int p = 0; p < 6; ++p) acco2[p] = 0ull;
#pragma unroll 4
            for (int k = 0; k < TT; ++k) {
                const float v = sm[OFF_V + k * LDA + hc + lane];
                u64x vp; PKDUP(vp, v);
                const float* arow = sm + OFF_S + k * LDSS + q0;
#pragma unroll
                for (int b = 0; b < 3; ++b) {
                    ulonglong2 a2 = *(const ulonglong2*)(arow + 4 * b);
                    FMA2(acco2[2*b + 0], a2.x, vp);
                    FMA2(acco2[2*b + 1], a2.y, vp);
                }
            }
#pragma unroll
            for (int p = 0; p < 6; ++p) {
                float lo, hi; UNPK(lo, hi, acco2[p]);
                sm[OFF_O + (q0 + 2*p + 0) * HDIM + lane] = lo;
                sm[OFF_O + (q0 + 2*p + 1) * HDIM + lane] = hi;
            }
        }
        __syncthreads();

        // stage Wo[:, hc:hc+32] and accumulate y += O_h @ Wo_h^T  (FFMA2)
        stage_w32(sm, Wo, hc, t);
        __syncthreads();
        {
#pragma unroll
            for (int c4 = 0; c4 < 8; ++c4) {
                float4 ov[ROWS];
#pragma unroll
                for (int i = 0; i < ROWS; ++i)
                    ov[i] = *(const float4*)(sm + OFF_O + (q0 + i) * HDIM + c4 * 4);
#pragma unroll
                for (int cc = 0; cc < 4; ++cc) {
                    const int cl = c4 * 4 + cc;
                    ulonglong2 w2 = *(const ulonglong2*)(sm + OFF_W + cl * LDW + SWZ(cl, jb));
#pragma unroll
                    for (int i = 0; i < ROWS; ++i) {
                        const float o = ((const float*)&ov[i])[cc];
                        u64x op; PKDUP(op, o);
                        FMA2(accy2[i][0], op, w2.x);
                        FMA2(accy2[i][1], op, w2.y);
                    }
                }
            }
        }
        __syncthreads();   // before next head reuses S_T / O / Ws
    }

    // ---- epilogue: y = accy + bo ----
    {
        const float4 b4 = *(const float4*)(bo + jb);
        u64x b01, b23; PK(b01, b4.x, b4.y); PK(b23, b4.z, b4.w);
#pragma unroll
        for (int i = 0; i < ROWS; ++i) {
            ulonglong2 r2;
            ADD2(r2.x, accy2[i][0], b01);
            ADD2(r2.y, accy2[i][1], b23);
            *(ulonglong2*)(yg + (q0 + i) * CCH + jb) = r2;
        }
    }
}

extern "C" void kernel_launch(void* const* d_in, const int* in_sizes, int n_in,
                              void* d_out, int out_size)
{
    const float* x  = (const float*)d_in[0];
    const float* Wq = (const float*)d_in[1];
    const float* bq = (const float*)d_in[2];
    const float* Wk = (const float*)d_in[3];
    const float* bk = (const float*)d_in[4];
    const float* Wv = (const float*)d_in[5];
    const float* bv = (const float*)d_in[6];
    const float* Wo = (const float*)d_in[7];
    const float* bo = (const float*)d_in[8];
    float* y = (float*)d_out;

    const int nodes = in_sizes[0] / (TT * CCH);   // 4096

    cudaFuncSetAttribute(spatial_attn_kernel,
                         cudaFuncAttributeMaxDynamicSharedMemorySize, SMEM_BYTES);
    spatial_attn_kernel<<<nodes, NT, SMEM_BYTES>>>(x, Wq, bq, Wk, bk, Wv, bv, Wo, bo, y);
}

// round 11
// speedup vs baseline: 1.3635x; 1.3635x over previous
#include <cuda_runtime.h>
#include <cuda_bf16.h>
#include <cstdint>

// SpatialAttention fused kernel, round 11:
//  - QKV projections via mma.sync.m16n8k16 bf16 (compensated hi/lo split, fp32 accum)
//    NOTE: tcgen05 PTX is rejected by the harness toolchain (compute_103 virtual arch);
//    mma.sync is baseline PTX ISA and compiles.
//  - attention (QK^T, query-axis softmax, A*V) + Wo projection: round-8 FFMA2 path (known-good).
// One CTA (512 thr) per node.

#define TT 96
#define CCH 128
#define NH 4
#define HDIM 32
#define LDA 132
#define LDSS 100
#define LDW 128
#define NT 512
#define ROWS 6

// ---- float offsets (phase B + QKV dest) ----
#define OFF_Q 0
#define OFF_K 12672
#define OFF_V 25344
#define OFF_S 38016
#define OFF_O 47616
#define OFF_W 50688
#define SMEM_FLOATS 54784
#define SMEM_BYTES (SMEM_FLOATS * 4)   // 219136

// ---- staging byte offsets (inside [152064, 209408), free during phase B) ----
#define XH_B 152064       // 96 rows x 64 bf16 (128B/row, swizzled) = 12288
#define XL_B 164352
#define WH_B 176640       // 128 rows x 64 bf16 = 16384
#define WL_B 193024

#define SWZ(c, j) ((j) ^ ((c) & 28))

typedef unsigned long long u64x;

#define FMA2(d, a, b) \
    asm("fma.rn.f32x2 %0, %1, %2, %0;" : "+l"(d) : "l"(a), "l"(b))
#define ADD2(d, a, b) \
    asm("add.rn.f32x2 %0, %1, %2;" : "=l"(d) : "l"(a), "l"(b))
#define PKDUP(d, v) do { unsigned _u = __float_as_uint(v); \
    asm("mov.b64 %0, {%1, %1};" : "=l"(d) : "r"(_u)); } while (0)
#define PK(d, xlo, xhi) \
    asm("mov.b64 %0, {%1, %2};" : "=l"(d) : "r"(__float_as_uint(xlo)), "r"(__float_as_uint(xhi)))
#define UNPK(xlo, xhi, d) do { unsigned _l, _h; \
    asm("mov.b64 {%0, %1}, %2;" : "=r"(_l), "=r"(_h) : "l"(d)); \
    xlo = __uint_as_float(_l); xhi = __uint_as_float(_h); } while (0)

#define LDSM4(r0, r1, r2, r3, a) \
    asm volatile("ldmatrix.sync.aligned.m8n8.x4.shared.b16 {%0,%1,%2,%3}, [%4];" \
        : "=r"(r0), "=r"(r1), "=r"(r2), "=r"(r3) : "r"(a))

#define MMA16816(d, a, b0, b1) \
    asm volatile("mma.sync.aligned.m16n8k16.row.col.f32.bf16.bf16.f32 " \
        "{%0,%1,%2,%3}, {%4,%5,%6,%7}, {%8,%9}, {%0,%1,%2,%3};" \
        : "+f"((d)[0]), "+f"((d)[1]), "+f"((d)[2]), "+f"((d)[3]) \
        : "r"((a)[0]), "r"((a)[1]), "r"((a)[2]), "r"((a)[3]), "r"(b0), "r"(b1))

__device__ __forceinline__ uint32_t smem_u32(const void* p) {
    uint32_t a;
    asm("{ .reg .u64 t; cvta.to.shared.u64 t, %1; cvt.u32.u64 %0, t; }" : "=r"(a) : "l"(p));
    return a;
}

// bf16 hi/lo pack of two floats
__device__ __forceinline__ uint32_t pk_bf2(float a, float b, uint32_t& lo) {
    __nv_bfloat16 ha = __float2bfloat16(a), hb = __float2bfloat16(b);
    __nv_bfloat16 la = __float2bfloat16(a - __bfloat162float(ha));
    __nv_bfloat16 lb = __float2bfloat16(b - __bfloat162float(hb));
    lo = (uint32_t)__bfloat16_as_ushort(la) | ((uint32_t)__bfloat16_as_ushort(lb) << 16);
    return (uint32_t)__bfloat16_as_ushort(ha) | ((uint32_t)__bfloat16_as_ushort(hb) << 16);
}

// ---- precomputed bf16 hi/lo weights (row-major [n=128][k=128]) ----
__device__ __align__(16) __nv_bfloat16 g_WH[3][CCH * CCH];
__device__ __align__(16) __nv_bfloat16 g_WL[3][CCH * CCH];

__global__ void wsplit_kernel(const float* __restrict__ Wq,
                              const float* __restrict__ Wk,
                              const float* __restrict__ Wv)
{
    int i = blockIdx.x * blockDim.x + threadIdx.x;
    if (i >= 3 * CCH * CCH) return;
    int m = i / (CCH * CCH), e = i % (CCH * CCH);
    const float* W = (m == 0) ? Wq : (m == 1) ? Wk : Wv;
    float w = W[e];
    __nv_bfloat16 h = __float2bfloat16(w);
    g_WH[m][e] = h;
    g_WL[m][e] = __float2bfloat16(w - __bfloat162float(h));
}

// ldmatrix source addresses (rows of 128B = 8 chunks of 16B, swizzle ch ^= row&7)
__device__ __forceinline__ uint32_t a_addr(uint32_t base, int m0, int c2, int lane) {
    int sub = lane >> 3, rr = lane & 7;
    int row = m0 + ((sub & 1) << 3) + rr;
    int ch  = c2 + (sub >> 1);
    return base + row * 128 + (((ch ^ (row & 7)) & 7) << 4);
}
__device__ __forceinline__ uint32_t b_addr(uint32_t base, int n0, int c2, int lane) {
    int sub = lane >> 3, rr = lane & 7;
    int row = n0 + ((sub >> 1) << 3) + rr;
    int ch  = c2 + (sub & 1);
    return base + row * 128 + (((ch ^ (row & 7)) & 7) << 4);
}

// fp32 Wo staging (swizzled, conflict-free), NT=512
__device__ __forceinline__ void stage_wo(float* sm, const float* __restrict__ W, int c0, int t)
{
    const int ccg = t & 7;
    const int jr  = t >> 3;
#pragma unroll
    for (int rep = 0; rep < 2; ++rep) {
        const int j = jr + rep * 64;
        float4 w = *(const float4*)(W + j * CCH + c0 + ccg * 4);
        const int r0 = ccg * 4;
        sm[OFF_W + (r0 + 0) * LDW + SWZ(r0 + 0, j)] = w.x;
        sm[OFF_W + (r0 + 1) * LDW + SWZ(r0 + 1, j)] = w.y;
        sm[OFF_W + (r0 + 2) * LDW + SWZ(r0 + 2, j)] = w.z;
        sm[OFF_W + (r0 + 3) * LDW + SWZ(r0 + 3, j)] = w.w;
    }
}

__global__ __launch_bounds__(NT, 1)
void spatial_attn_kernel(const float* __restrict__ x,
                         const float* __restrict__ bq,
                         const float* __restrict__ bk,
                         const float* __restrict__ bv,
                         const float* __restrict__ Wo, const float* __restrict__ bo,
                         float* __restrict__ out)
{
    extern __shared__ float sm[];
    char* smb = (char*)sm;
    const uint32_t smb0 = smem_u32(sm);
    const int t    = threadIdx.x;
    const int lane = t & 31;
    const int qg   = t >> 5;
    const int q0   = qg * ROWS;
    const size_t gbase = (size_t)blockIdx.x * (TT * CCH);
    const float* xg = x + gbase;
    float* yg = out + gbase;

    // warp MMA tile: m-group (48 rows) x n-group (16 cols)
    const int mg  = qg & 1;
    const int ng  = qg >> 1;
    const int m0w = mg * 48;
    const int n0w = ng * 16;

    // ======== phase A: QKV via mma.sync bf16 split ========
#pragma unroll 1
    for (int m = 0; m < 3; ++m) {
        float acc[3][2][4];
#pragma unroll
        for (int i = 0; i < 3; ++i)
#pragma unroll
            for (int j = 0; j < 2; ++j)
#pragma unroll
                for (int c = 0; c < 4; ++c) acc[i][j][c] = 0.f;

#pragma unroll 1
        for (int kh = 0; kh < 2; ++kh) {
            // stage X half (hi/lo bf16, swizzled) — 384 threads
            if (t < 384) {
                const int row = t >> 2, g = t & 3;
                const float4* src = (const float4*)xg + row * 32 + kh * 16 + g * 4;
                float4 f0 = src[0], f1 = src[1], f2 = src[2], f3 = src[3];
                uint4 h0, l0, h1, l1;
                h0.x = pk_bf2(f0.x, f0.y, l0.x); h0.y = pk_bf2(f0.z, f0.w, l0.y);
                h0.z = pk_bf2(f1.x, f1.y, l0.z); h0.w = pk_bf2(f1.z, f1.w, l0.w);
                h1.x = pk_bf2(f2.x, f2.y, l1.x); h1.y = pk_bf2(f2.z, f2.w, l1.y);
                h1.z = pk_bf2(f3.x, f3.y, l1.z); h1.w = pk_bf2(f3.z, f3.w, l1.w);
                const int c0 = (2 * g) ^ (row & 7);
                const int c1 = (2 * g + 1) ^ (row & 7);
                *(uint4*)(smb + XH_B + row * 128 + c0 * 16) = h0;
                *(uint4*)(smb + XH_B + row * 128 + c1 * 16) = h1;
                *(uint4*)(smb + XL_B + row * 128 + c0 * 16) = l0;
                *(uint4*)(smb + XL_B + row * 128 + c1 * 16) = l1;
            }
            // stage W half (hi/lo bf16, swizzled) — all 512 threads, 2 chunks each
            {
                const int n = t >> 2;
                const int cb = (t & 3) * 2;
#pragma unroll
                for (int q = 0; q < 2; ++q) {
                    const int cl = cb + q;
                    const int swc = (cl ^ (n & 7)) & 7;
                    uint4 vh = *(const uint4*)((const char*)g_WH[m] + n * 256 + kh * 128 + cl * 16);
                    uint4 vl = *(const uint4*)((const char*)g_WL[m] + n * 256 + kh * 128 + cl * 16);
                    *(uint4*)(smb + WH_B + n * 128 + swc * 16) = vh;
                    *(uint4*)(smb + WL_B + n * 128 + swc * 16) = vl;
                }
            }
            __syncthreads();

            // 4 k-steps of 16: acc += Ah*Bh + Ah*Bl + Al*Bh
#pragma unroll
            for (int kk = 0; kk < 4; ++kk) {
                const int c2 = 2 * kk;
                uint32_t Ah[3][4], Al[3][4], Bh[4], Bl[4];
#pragma unroll
                for (int i = 0; i < 3; ++i) {
                    LDSM4(Ah[i][0], Ah[i][1], Ah[i][2], Ah[i][3],
                          a_addr(smb0 + XH_B, m0w + 16 * i, c2, lane));
                    LDSM4(Al[i][0], Al[i][1], Al[i][2], Al[i][3],
                          a_addr(smb0 + XL_B, m0w + 16 * i, c2, lane));
                }
                LDSM4(Bh[0], Bh[1], Bh[2], Bh[3], b_addr(smb0 + WH_B, n0w, c2, lane));
                LDSM4(Bl[0], Bl[1], Bl[2], Bl[3], b_addr(smb0 + WL_B, n0w, c2, lane));
#pragma unroll
                for (int i = 0; i < 3; ++i)
#pragma unroll
                    for (int j = 0; j < 2; ++j) {
                        MMA16816(acc[i][j], Ah[i], Bh[2 * j], Bh[2 * j + 1]);
                        MMA16816(acc[i][j], Ah[i], Bl[2 * j], Bl[2 * j + 1]);
                        MMA16816(acc[i][j], Al[i], Bh[2 * j], Bh[2 * j + 1]);
                    }
            }
            __syncthreads();   // staging buffers reusable
        }

        // write fragments (+bias) to fp32 Q/K/V dest
        {
            const float* bias = (m == 0) ? bq : (m == 1) ? bk : bv;
            const int off = (m == 0) ? OFF_Q : (m == 1) ? OFF_K : OFF_V;
#pragma unroll
            for (int j = 0; j < 2; ++j) {
                const int jc = n0w + 8 * j + 2 * (lane & 3);
                const float2 bb = *(const float2*)(bias + jc);
#pragma unroll
                for (int i = 0; i < 3; ++i) {
                    const int r = m0w + 16 * i + (lane >> 2);
                    float2 v0, v1;
                    v0.x = acc[i][j][0] + bb.x; v0.y = acc[i][j][1] + bb.y;
                    v1.x = acc[i][j][2] + bb.x; v1.y = acc[i][j][3] + bb.y;
                    *(float2*)(sm + off + r * LDA + jc)       = v0;
                    *(float2*)(sm + off + (r + 8) * LDA + jc) = v1;
                }
            }
        }
    }
    __syncthreads();   // Q/K/V ready

    // ======== phase B: attention + Wo (round-8 FFMA2 path) ========
    const float scale = 0.17677669529663687f;  // 1/sqrt(32)
    u64x accy2[ROWS][2];
#pragma unroll
    for (int i = 0; i < ROWS; ++i) { accy2[i][0] = 0ull; accy2[i][1] = 0ull; }
    const int jb = lane * 4;

#pragma unroll 1
    for (int h = 0; h < NH; ++h) {
        const int hc = h * HDIM;

        // S_T[k][q] = scale * (Q[q,hc:] . K[k,hc:])
        {
            u64x acc2[ROWS][3];
#pragma unroll
            for (int i = 0; i < ROWS; ++i)
#pragma unroll
                for (int j = 0; j < 3; ++j) acc2[i][j] = 0ull;
            const int kb = lane * 3;
#pragma unroll
            for (int c4 = 0; c4 < 8; ++c4) {
                ulonglong2 qv[ROWS];
#pragma unroll
                for (int i = 0; i < ROWS; ++i)
                    qv[i] = *(const ulonglong2*)(sm + OFF_Q + (q0 + i) * LDA + hc + c4 * 4);
#pragma unroll
                for (int j = 0; j < 3; ++j) {
                    ulonglong2 kv = *(const ulonglong2*)(sm + OFF_K + (kb + j) * LDA + hc + c4 * 4);
#pragma unroll
                    for (int i = 0; i < ROWS; ++i) {
                        FMA2(acc2[i][j], qv[i].x, kv.x);
                        FMA2(acc2[i][j], qv[i].y, kv.y);
                    }
                }
            }
#pragma unroll
            for (int j = 0; j < 3; ++j)
#pragma unroll
                for (int i = 0; i < ROWS; ++i) {
                    float lo, hi; UNPK(lo, hi, acc2[i][j]);
                    sm[OFF_S + (kb + j) * LDSS + q0 + i] = (lo + hi) * scale;
                }
        }
        __syncthreads();

        // softmax over q (axis=-2)
        {
#pragma unroll
            for (int r = 0; r < ROWS; ++r) {
                const int k = qg * ROWS + r;
                float v0 = sm[OFF_S + k * LDSS + lane];
                float v1 = sm[OFF_S + k * LDSS + lane + 32];
                float v2 = sm[OFF_S + k * LDSS + lane + 64];
                float mx = fmaxf(v0, fmaxf(v1, v2));
#pragma unroll
                for (int o = 16; o; o >>= 1) mx = fmaxf(mx, __shfl_xor_sync(0xffffffffu, mx, o));
                float e0 = __expf(v0 - mx), e1 = __expf(v1 - mx), e2 = __expf(v2 - mx);
                float s = e0 + e1 + e2;
#pragma unroll
                for (int o = 16; o; o >>= 1) s += __shfl_xor_sync(0xffffffffu, s, o);
                const float inv = 1.f / s;
                sm[OFF_S + k * LDSS + lane]      = e0 * inv;
                sm[OFF_S + k * LDSS + lane + 32] = e1 * inv;
                sm[OFF_S + k * LDSS + lane + 64] = e2 * inv;
            }
        }
        __syncthreads();

        // O[q][d] = sum_k A_T[k][q] * V[k][hc+d]
        {
            u64x acco2[3];
            acco2[0] = 0ull; acco2[1] = 0ull; acco2[2] = 0ull;
#pragma unroll 4
            for (int k = 0; k < TT; ++k) {
                const float v = sm[OFF_V + k * LDA + hc + lane];
                u64x vp; PKDUP(vp, v);
                const u64x* ap = (const u64x*)(sm + OFF_S + k * LDSS + q0);
                FMA2(acco2[0], ap[0], vp);
                FMA2(acco2[1], ap[1], vp);
                FMA2(acco2[2], ap[2], vp);
            }
#pragma unroll
            for (int p = 0; p < 3; ++p) {
                float lo, hi; UNPK(lo, hi, acco2[p]);
                sm[OFF_O + (q0 + 2 * p + 0) * HDIM + lane] = lo;
                sm[OFF_O + (q0 + 2 * p + 1) * HDIM + lane] = hi;
            }
        }
        __syncthreads();

        // y += O_h @ Wo_h^T
        stage_wo(sm, Wo, hc, t);
        __syncthreads();
        {
#pragma unroll
            for (int c4 = 0; c4 < 8; ++c4) {
                float4 ov[ROWS];
#pragma unroll
                for (int i = 0; i < ROWS; ++i)
                    ov[i] = *(const float4*)(sm + OFF_O + (q0 + i) * HDIM + c4 * 4);
#pragma unroll
                for (int cc = 0; cc < 4; ++cc) {
                    const int cl = c4 * 4 + cc;
                    ulonglong2 w2 = *(const ulonglong2*)(sm + OFF_W + cl * LDW + SWZ(cl, jb));
#pragma unroll
                    for (int i = 0; i < ROWS; ++i) {
                        const float o = ((const float*)&ov[i])[cc];
                        u64x op; PKDUP(op, o);
                        FMA2(accy2[i][0], op, w2.x);
                        FMA2(accy2[i][1], op, w2.y);
                    }
                }
            }
        }
        __syncthreads();
    }

    // ---- epilogue: y = accy + bo ----
    {
        const float4 b4 = *(const float4*)(bo + jb);
        u64x b01, b23; PK(b01, b4.x, b4.y); PK(b23, b4.z, b4.w);
#pragma unroll
        for (int i = 0; i < ROWS; ++i) {
            ulonglong2 r2;
            ADD2(r2.x, accy2[i][0], b01);
            ADD2(r2.y, accy2[i][1], b23);
            *(ulonglong2*)(yg + (q0 + i) * CCH + jb) = r2;
        }
    }
}

extern "C" void kernel_launch(void* const* d_in, const int* in_sizes, int n_in,
                              void* d_out, int out_size)
{
    const float* x  = (const float*)d_in[0];
    const float* Wq = (const float*)d_in[1];
    const float* bq = (const float*)d_in[2];
    const float* Wk = (const float*)d_in[3];
    const float* bk = (const float*)d_in[4];
    const float* Wv = (const float*)d_in[5];
    const float* bv = (const float*)d_in[6];
    const float* Wo = (const float*)d_in[7];
    const float* bo = (const float*)d_in[8];
    float* y = (float*)d_out;

    const int nodes = in_sizes[0] / (TT * CCH);   // 4096

    wsplit_kernel<<<(3 * CCH * CCH + 255) / 256, 256>>>(Wq, Wk, Wv);

    cudaFuncSetAttribute(spatial_attn_kernel,
                         cudaFuncAttributeMaxDynamicSharedMemorySize, SMEM_BYTES);
    spatial_attn_kernel<<<nodes, NT, SMEM_BYTES>>>(x, bq, bk, bv, Wo, bo, y);
}

// round 12
// speedup vs baseline: 1.4301x; 1.0489x over previous
#include <cuda_runtime.h>
#include <cuda_bf16.h>
#include <cstdint>

// SpatialAttention fused kernel, round 12:
//  - QKV projections via mma.sync.m16n8k16 bf16 (compensated hi/lo split, fp32 accum)  [round-11, validated]
//  - attention (QK^T, query-axis softmax, A*V): FFMA2
//  - Wo projection via mma.sync: A*V writes O directly as bf16 hi/lo into the dead S_T
//    region; Wo head-slices staged there too; y accumulated in MMA fragments across heads.
// One CTA (512 thr) per node.

#define TT 96
#define CCH 128
#define NH 4
#define HDIM 32
#define LDA 132
#define LDSS 98      // S_T row stride: 3*98*lane = 6*lane mod 32 -> 2-way store conflict (was 4-way)
#define NT 512
#define ROWS 6

// ---- float offsets ----
#define OFF_Q 0
#define OFF_K 12672
#define OFF_V 25344
#define OFF_S 38016              // 96*98 = 9408 floats -> ends 47424
// ---- phase-A staging byte offsets (region free during phase B mainloop) ----
#define XH_B 152064              // 96 rows x 128B
#define XL_B 164352
#define WH_B 176640              // 128 rows x 128B
#define WL_B 193024
#define SMEM_BYTES 209408
// ---- Wo-MMA staging (inside dead S_T region, bytes) ----
#define OH_B  152064             // O hi: 96 rows x 64B
#define OL_B  158208             // O lo
#define WOH_B 164352             // Wo slice hi: 128 rows x 64B
#define WOL_B 172544             // Wo slice lo  (ends 180736 < 189696 = S end)

typedef unsigned long long u64x;

#define FMA2(d, a, b) \
    asm("fma.rn.f32x2 %0, %1, %2, %0;" : "+l"(d) : "l"(a), "l"(b))
#define PKDUP(d, v) do { unsigned _u = __float_as_uint(v); \
    asm("mov.b64 %0, {%1, %1};" : "=l"(d) : "r"(_u)); } while (0)
#define UNPK(xlo, xhi, d) do { unsigned _l, _h; \
    asm("mov.b64 {%0, %1}, %2;" : "=r"(_l), "=r"(_h) : "l"(d)); \
    xlo = __uint_as_float(_l); xhi = __uint_as_float(_h); } while (0)

#define LDSM4(r0, r1, r2, r3, a) \
    asm volatile("ldmatrix.sync.aligned.m8n8.x4.shared.b16 {%0,%1,%2,%3}, [%4];" \
        : "=r"(r0), "=r"(r1), "=r"(r2), "=r"(r3) : "r"(a))

#define MMA16816(d, a, b0, b1) \
    asm volatile("mma.sync.aligned.m16n8k16.row.col.f32.bf16.bf16.f32 " \
        "{%0,%1,%2,%3}, {%4,%5,%6,%7}, {%8,%9}, {%0,%1,%2,%3};" \
        : "+f"((d)[0]), "+f"((d)[1]), "+f"((d)[2]), "+f"((d)[3]) \
        : "r"((a)[0]), "r"((a)[1]), "r"((a)[2]), "r"((a)[3]), "r"(b0), "r"(b1))

__device__ __forceinline__ uint32_t smem_u32(const void* p) {
    uint32_t a;
    asm("{ .reg .u64 t; cvta.to.shared.u64 t, %1; cvt.u32.u64 %0, t; }" : "=r"(a) : "l"(p));
    return a;
}

__device__ __forceinline__ uint32_t pk_bf2(float a, float b, uint32_t& lo) {
    __nv_bfloat16 ha = __float2bfloat16(a), hb = __float2bfloat16(b);
    __nv_bfloat16 la = __float2bfloat16(a - __bfloat162float(ha));
    __nv_bfloat16 lb = __float2bfloat16(b - __bfloat162float(hb));
    lo = (uint32_t)__bfloat16_as_ushort(la) | ((uint32_t)__bfloat16_as_ushort(lb) << 16);
    return (uint32_t)__bfloat16_as_ushort(ha) | ((uint32_t)__bfloat16_as_ushort(hb) << 16);
}

// ---- precomputed bf16 hi/lo weights (row-major [n=128][k=128]); index 3 = Wo ----
__device__ __align__(16) __nv_bfloat16 g_WH[4][CCH * CCH];
__device__ __align__(16) __nv_bfloat16 g_WL[4][CCH * CCH];

__global__ void wsplit_kernel(const float* __restrict__ Wq,
                              const float* __restrict__ Wk,
                              const float* __restrict__ Wv,
                              const float* __restrict__ Wo)
{
    int i = blockIdx.x * blockDim.x + threadIdx.x;
    if (i >= 4 * CCH * CCH) return;
    int m = i / (CCH * CCH), e = i % (CCH * CCH);
    const float* W = (m == 0) ? Wq : (m == 1) ? Wk : (m == 2) ? Wv : Wo;
    float w = W[e];
    __nv_bfloat16 h = __float2bfloat16(w);
    g_WH[m][e] = h;
    g_WL[m][e] = __float2bfloat16(w - __bfloat162float(h));
}

// 128B-row ldmatrix addressing (phase A, validated)
__device__ __forceinline__ uint32_t a_addr(uint32_t base, int m0, int c2, int lane) {
    int sub = lane >> 3, rr = lane & 7;
    int row = m0 + ((sub & 1) << 3) + rr;
    int ch  = c2 + (sub >> 1);
    return base + row * 128 + (((ch ^ (row & 7)) & 7) << 4);
}
__device__ __forceinline__ uint32_t b_addr(uint32_t base, int n0, int c2, int lane) {
    int sub = lane >> 3, rr = lane & 7;
    int row = n0 + ((sub >> 1) << 3) + rr;
    int ch  = c2 + (sub & 1);
    return base + row * 128 + (((ch ^ (row & 7)) & 7) << 4);
}
// 64B-row ldmatrix addressing (Wo-MMA): swizzle chunk ^= (row>>1)&3
__device__ __forceinline__ uint32_t a64_addr(uint32_t base, int m0, int c2, int lane) {
    int sub = lane >> 3, rr = lane & 7;
    int row = m0 + ((sub & 1) << 3) + rr;
    int ch  = c2 + (sub >> 1);
    return base + row * 64 + (((ch ^ ((row >> 1) & 3)) & 3) << 4);
}
__device__ __forceinline__ uint32_t b64_addr(uint32_t base, int n0, int c2, int lane) {
    int sub = lane >> 3, rr = lane & 7;
    int row = n0 + ((sub >> 1) << 3) + rr;
    int ch  = c2 + (sub & 1);
    return base + row * 64 + (((ch ^ ((row >> 1) & 3)) & 3) << 4);
}

__global__ __launch_bounds__(NT, 1)
void spatial_attn_kernel(const float* __restrict__ x,
                         const float* __restrict__ bq,
                         const float* __restrict__ bk,
                         const float* __restrict__ bv,
                         const float* __restrict__ bo,
                         float* __restrict__ out)
{
    extern __shared__ float sm[];
    char* smb = (char*)sm;
    const uint32_t smb0 = smem_u32(sm);
    const int t    = threadIdx.x;
    const int lane = t & 31;
    const int qg   = t >> 5;
    const int q0   = qg * ROWS;
    const size_t gbase = (size_t)blockIdx.x * (TT * CCH);
    const float* xg = x + gbase;
    float* yg = out + gbase;

    // warp MMA tile: m-group (48 rows) x n-group (16 cols) — shared by QKV and Wo MMAs
    const int m0w = (qg & 1) * 48;
    const int n0w = (qg >> 1) * 16;

    // ======== phase A: QKV via mma.sync bf16 split (round-11, validated) ========
#pragma unroll 1
    for (int m = 0; m < 3; ++m) {
        float acc[3][2][4];
#pragma unroll
        for (int i = 0; i < 3; ++i)
#pragma unroll
            for (int j = 0; j < 2; ++j)
#pragma unroll
                for (int c = 0; c < 4; ++c) acc[i][j][c] = 0.f;

#pragma unroll 1
        for (int kh = 0; kh < 2; ++kh) {
            if (t < 384) {
                const int row = t >> 2, g = t & 3;
                const float4* src = (const float4*)xg + row * 32 + kh * 16 + g * 4;
                float4 f0 = src[0], f1 = src[1], f2 = src[2], f3 = src[3];
                uint4 h0, l0, h1, l1;
                h0.x = pk_bf2(f0.x, f0.y, l0.x); h0.y = pk_bf2(f0.z, f0.w, l0.y);
                h0.z = pk_bf2(f1.x, f1.y, l0.z); h0.w = pk_bf2(f1.z, f1.w, l0.w);
                h1.x = pk_bf2(f2.x, f2.y, l1.x); h1.y = pk_bf2(f2.z, f2.w, l1.y);
                h1.z = pk_bf2(f3.x, f3.y, l1.z); h1.w = pk_bf2(f3.z, f3.w, l1.w);
                const int c0 = (2 * g) ^ (row & 7);
                const int c1 = (2 * g + 1) ^ (row & 7);
                *(uint4*)(smb + XH_B + row * 128 + c0 * 16) = h0;
                *(uint4*)(smb + XH_B + row * 128 + c1 * 16) = h1;
                *(uint4*)(smb + XL_B + row * 128 + c0 * 16) = l0;
                *(uint4*)(smb + XL_B + row * 128 + c1 * 16) = l1;
            }
            {
                const int n = t >> 2;
                const int cb = (t & 3) * 2;
#pragma unroll
                for (int q = 0; q < 2; ++q) {
                    const int cl = cb + q;
                    const int swc = (cl ^ (n & 7)) & 7;
                    uint4 vh = *(const uint4*)((const char*)g_WH[m] + n * 256 + kh * 128 + cl * 16);
                    uint4 vl = *(const uint4*)((const char*)g_WL[m] + n * 256 + kh * 128 + cl * 16);
                    *(uint4*)(smb + WH_B + n * 128 + swc * 16) = vh;
                    *(uint4*)(smb + WL_B + n * 128 + swc * 16) = vl;
                }
            }
            __syncthreads();

#pragma unroll
            for (int kk = 0; kk < 4; ++kk) {
                const int c2 = 2 * kk;
                uint32_t Ah[3][4], Al[3][4], Bh[4], Bl[4];
#pragma unroll
                for (int i = 0; i < 3; ++i) {
                    LDSM4(Ah[i][0], Ah[i][1], Ah[i][2], Ah[i][3],
                          a_addr(smb0 + XH_B, m0w + 16 * i, c2, lane));
                    LDSM4(Al[i][0], Al[i][1], Al[i][2], Al[i][3],
                          a_addr(smb0 + XL_B, m0w + 16 * i, c2, lane));
                }
                LDSM4(Bh[0], Bh[1], Bh[2], Bh[3], b_addr(smb0 + WH_B, n0w, c2, lane));
                LDSM4(Bl[0], Bl[1], Bl[2], Bl[3], b_addr(smb0 + WL_B, n0w, c2, lane));
#pragma unroll
                for (int i = 0; i < 3; ++i)
#pragma unroll
                    for (int j = 0; j < 2; ++j) {
                        MMA16816(acc[i][j], Ah[i], Bh[2 * j], Bh[2 * j + 1]);
                        MMA16816(acc[i][j], Ah[i], Bl[2 * j], Bl[2 * j + 1]);
                        MMA16816(acc[i][j], Al[i], Bh[2 * j], Bh[2 * j + 1]);
                    }
            }
            __syncthreads();
        }

        {
            const float* bias = (m == 0) ? bq : (m == 1) ? bk : bv;
            const int off = (m == 0) ? OFF_Q : (m == 1) ? OFF_K : OFF_V;
#pragma unroll
            for (int j = 0; j < 2; ++j) {
                const int jc = n0w + 8 * j + 2 * (lane & 3);
                const float2 bb = *(const float2*)(bias + jc);
#pragma unroll
                for (int i = 0; i < 3; ++i) {
                    const int r = m0w + 16 * i + (lane >> 2);
                    float2 v0, v1;
                    v0.x = acc[i][j][0] + bb.x; v0.y = acc[i][j][1] + bb.y;
                    v1.x = acc[i][j][2] + bb.x; v1.y = acc[i][j][3] + bb.y;
                    *(float2*)(sm + off + r * LDA + jc)       = v0;
                    *(float2*)(sm + off + (r + 8) * LDA + jc) = v1;
                }
            }
        }
    }
    __syncthreads();   // Q/K/V ready

    // ======== phase B: attention (FFMA2) + Wo via MMA ========
    const float scale = 0.17677669529663687f;  // 1/sqrt(32)
    float accy[3][2][4];                       // y fragments, accumulated across heads
#pragma unroll
    for (int i = 0; i < 3; ++i)
#pragma unroll
        for (int j = 0; j < 2; ++j)
#pragma unroll
            for (int c = 0; c < 4; ++c) accy[i][j][c] = 0.f;

#pragma unroll 1
    for (int h = 0; h < NH; ++h) {
        const int hc = h * HDIM;

        // S_T[k][q] = scale * (Q[q,hc:] . K[k,hc:])
        {
            u64x acc2[ROWS][3];
#pragma unroll
            for (int i = 0; i < ROWS; ++i)
#pragma unroll
                for (int j = 0; j < 3; ++j) acc2[i][j] = 0ull;
            const int kb = lane * 3;
#pragma unroll
            for (int c4 = 0; c4 < 8; ++c4) {
                ulonglong2 qv[ROWS];
#pragma unroll
                for (int i = 0; i < ROWS; ++i)
                    qv[i] = *(const ulonglong2*)(sm + OFF_Q + (q0 + i) * LDA + hc + c4 * 4);
#pragma unroll
                for (int j = 0; j < 3; ++j) {
                    ulonglong2 kv = *(const ulonglong2*)(sm + OFF_K + (kb + j) * LDA + hc + c4 * 4);
#pragma unroll
                    for (int i = 0; i < ROWS; ++i) {
                        FMA2(acc2[i][j], qv[i].x, kv.x);
                        FMA2(acc2[i][j], qv[i].y, kv.y);
                    }
                }
            }
#pragma unroll
            for (int j = 0; j < 3; ++j)
#pragma unroll
                for (int i = 0; i < ROWS; ++i) {
                    float lo, hi; UNPK(lo, hi, acc2[i][j]);
                    sm[OFF_S + (kb + j) * LDSS + q0 + i] = (lo + hi) * scale;
                }
        }
        __syncthreads();

        // softmax over q (axis=-2): each warp does 6 k-rows
        {
#pragma unroll
            for (int r = 0; r < ROWS; ++r) {
                const int k = qg * ROWS + r;
                float v0 = sm[OFF_S + k * LDSS + lane];
                float v1 = sm[OFF_S + k * LDSS + lane + 32];
                float v2 = sm[OFF_S + k * LDSS + lane + 64];
                float mx = fmaxf(v0, fmaxf(v1, v2));
#pragma unroll
                for (int o = 16; o; o >>= 1) mx = fmaxf(mx, __shfl_xor_sync(0xffffffffu, mx, o));
                float e0 = __expf(v0 - mx), e1 = __expf(v1 - mx), e2 = __expf(v2 - mx);
                float s = e0 + e1 + e2;
#pragma unroll
                for (int o = 16; o; o >>= 1) s += __shfl_xor_sync(0xffffffffu, s, o);
                const float inv = 1.f / s;
                sm[OFF_S + k * LDSS + lane]      = e0 * inv;
                sm[OFF_S + k * LDSS + lane + 32] = e1 * inv;
                sm[OFF_S + k * LDSS + lane + 64] = e2 * inv;
            }
        }
        __syncthreads();

        // A*V into registers (reads S_T + V only)
        u64x acco2[3];
        acco2[0] = 0ull; acco2[1] = 0ull; acco2[2] = 0ull;
        {
#pragma unroll 4
            for (int k = 0; k < TT; ++k) {
                const float v = sm[OFF_V + k * LDA + hc + lane];
                u64x vp; PKDUP(vp, v);
                const u64x* ap = (const u64x*)(sm + OFF_S + k * LDSS + q0);
                FMA2(acco2[0], ap[0], vp);
                FMA2(acco2[1], ap[1], vp);
                FMA2(acco2[2], ap[2], vp);
            }
        }
        __syncthreads();   // all S_T reads done -> region reusable for staging

        // stage O (bf16 hi/lo, 64B rows, swizzled) + Wo head-slice (pre-split, global)
        {
#pragma unroll
            for (int p = 0; p < 3; ++p) {
                float lo, hi; UNPK(lo, hi, acco2[p]);
#pragma unroll
                for (int e = 0; e < 2; ++e) {
                    const int q = q0 + 2 * p + e;
                    const float v = e ? hi : lo;
                    __nv_bfloat16 bh = __float2bfloat16(v);
                    __nv_bfloat16 bl = __float2bfloat16(v - __bfloat162float(bh));
                    const int ch = ((lane >> 3) ^ ((q >> 1) & 3)) & 3;
                    const int off = q * 64 + ch * 16 + (lane & 7) * 2;
                    *(__nv_bfloat16*)(smb + OH_B + off) = bh;
                    *(__nv_bfloat16*)(smb + OL_B + off) = bl;
                }
            }
            const int n  = t >> 2;
            const int ch = t & 3;
            const int swc = (ch ^ ((n >> 1) & 3)) & 3;
            uint4 vh = *(const uint4*)((const char*)g_WH[3] + n * 256 + hc * 2 + ch * 16);
            uint4 vl = *(const uint4*)((const char*)g_WL[3] + n * 256 + hc * 2 + ch * 16);
            *(uint4*)(smb + WOH_B + n * 64 + swc * 16) = vh;
            *(uint4*)(smb + WOL_B + n * 64 + swc * 16) = vl;
        }
        __syncthreads();

        // y += O_h @ Wo_h^T via mma.sync (k = 32 -> 2 k-steps)
        {
#pragma unroll
            for (int kk = 0; kk < 2; ++kk) {
                const int c2 = 2 * kk;
                uint32_t Ah[3][4], Al[3][4], Bh[4], Bl[4];
#pragma unroll
                for (int i = 0; i < 3; ++i) {
                    LDSM4(Ah[i][0], Ah[i][1], Ah[i][2], Ah[i][3],
                          a64_addr(smb0 + OH_B, m0w + 16 * i, c2, lane));
                    LDSM4(Al[i][0], Al[i][1], Al[i][2], Al[i][3],
                          a64_addr(smb0 + OL_B, m0w + 16 * i, c2, lane));
                }
                LDSM4(Bh[0], Bh[1], Bh[2], Bh[3], b64_addr(smb0 + WOH_B, n0w, c2, lane));
                LDSM4(Bl[0], Bl[1], Bl[2], Bl[3], b64_addr(smb0 + WOL_B, n0w, c2, lane));
#pragma unroll
                for (int i = 0; i < 3; ++i)
#pragma unroll
                    for (int j = 0; j < 2; ++j) {
                        MMA16816(accy[i][j], Ah[i], Bh[2 * j], Bh[2 * j + 1]);
                        MMA16816(accy[i][j], Ah[i], Bl[2 * j], Bl[2 * j + 1]);
                        MMA16816(accy[i][j], Al[i], Bh[2 * j], Bh[2 * j + 1]);
                    }
            }
        }
        __syncthreads();   // staging region reused by next head's S_T
    }

    // ---- epilogue: y = accy fragments + bo -> global ----
    {
#pragma unroll
        for (int j = 0; j < 2; ++j) {
            const int jc = n0w + 8 * j + 2 * (lane & 3);
            const float2 bb = *(const float2*)(bo + jc);
#pragma unroll
            for (int i = 0; i < 3; ++i) {
                const int r = m0w + 16 * i + (lane >> 2);
                float2 v0, v1;
                v0.x = accy[i][j][0] + bb.x; v0.y = accy[i][j][1] + bb.y;
                v1.x = accy[i][j][2] + bb.x; v1.y = accy[i][j][3] + bb.y;
                *(float2*)(yg + r * CCH + jc)       = v0;
                *(float2*)(yg + (r + 8) * CCH + jc) = v1;
            }
        }
    }
}

extern "C" void kernel_launch(void* const* d_in, const int* in_sizes, int n_in,
                              void* d_out, int out_size)
{
    const float* x  = (const float*)d_in[0];
    const float* Wq = (const float*)d_in[1];
    const float* bq = (const float*)d_in[2];
    const float* Wk = (const float*)d_in[3];
    const float* bk = (const float*)d_in[4];
    const float* Wv = (const float*)d_in[5];
    const float* bv = (const float*)d_in[6];
    const float* Wo = (const float*)d_in[7];
    const float* bo = (const float*)d_in[8];
    float* y = (float*)d_out;

    const int nodes = in_sizes[0] / (TT * CCH);   // 4096

    wsplit_kernel<<<(4 * CCH * CCH + 255) / 256, 256>>>(Wq, Wk, Wv, Wo);

    cudaFuncSetAttribute(spatial_attn_kernel,
                         cudaFuncAttributeMaxDynamicSharedMemorySize, SMEM_BYTES);
    spatial_attn_kernel<<<nodes, NT, SMEM_BYTES>>>(x, bq, bk, bv, bo, y);
}

// round 14
// speedup vs baseline: 1.6513x; 1.1547x over previous
#include <cuda_runtime.h>
#include <cuda_bf16.h>
#include <cstdint>

// SpatialAttention fused kernel, round 13:
//  - QKV projections via mma.sync bf16 hi/lo split (validated)
//  - QK^T + query-axis softmax: FFMA2 (validated)
//  - A*V via mma.sync with ldmatrix.trans (A stored bf16 hi/lo by softmax, V produced
//    bf16 hi/lo by phase-A epilogue) — removes the dominant smem-wavefront loop
//  - Wo projection via mma.sync (validated round-12 path)
// One CTA (512 thr) per node.

#define TT 96
#define CCH 128
#define NH 4
#define HDIM 32
#define LDA 132
#define LDSS 98
#define NT 512
#define ROWS 6

// ---- float offsets ----
#define OFF_Q 0                  // 96x132 fp32  [0, 50688) bytes
#define OFF_K 12672              // [50688, 101376)
#define OFF_S 37632              // S fp32 96x98 [150528, 188160)
// ---- byte offsets ----
#define VH_B 101376              // V hi bf16 [k][d] 96x256B  [101376, 125952)
#define VL_B 125952              // V lo                      [125952, 150528)
#define AH0_B 188160             // A hi, q<64 plane: 96x128B [188160, 200448)
#define AH1_B 200448             // A hi, q>=64 plane: 96x64B [200448, 206592)
#define AL0_B 206592             // A lo planes
#define AL1_B 218880             //                            ends 225024
#define SMEM_BYTES 225024
// ---- phase-A staging (dead regions during phase A mainloop) ----
#define XH_B 101376              // 96x128B
#define XL_B 113664
#define WH_B 125952              // 128x128B
#define WL_B 142336              // ends 158720 (overlaps V + S head: fine in phase A)
// ---- Wo staging (phase B, reuses A region after A*V) ----
#define OH_B  188160             // 96x64B
#define OL_B  194304
#define WOH_B 200448             // 128x64B
#define WOL_B 208640             // ends 216832

typedef unsigned long long u64x;

#define FMA2(d, a, b) \
    asm("fma.rn.f32x2 %0, %1, %2, %0;" : "+l"(d) : "l"(a), "l"(b))
#define UNPK(xlo, xhi, d) do { unsigned _l, _h; \
    asm("mov.b64 {%0, %1}, %2;" : "=r"(_l), "=r"(_h) : "l"(d)); \
    xlo = __uint_as_float(_l); xhi = __uint_as_float(_h); } while (0)

#define LDSM4(r0, r1, r2, r3, a) \
    asm volatile("ldmatrix.sync.aligned.m8n8.x4.shared.b16 {%0,%1,%2,%3}, [%4];" \
        : "=r"(r0), "=r"(r1), "=r"(r2), "=r"(r3) : "r"(a))
#define LDSM4T(r0, r1, r2, r3, a) \
    asm volatile("ldmatrix.sync.aligned.m8n8.x4.trans.shared.b16 {%0,%1,%2,%3}, [%4];" \
        : "=r"(r0), "=r"(r1), "=r"(r2), "=r"(r3) : "r"(a))

#define MMA16816(d, a, b0, b1) \
    asm volatile("mma.sync.aligned.m16n8k16.row.col.f32.bf16.bf16.f32 " \
        "{%0,%1,%2,%3}, {%4,%5,%6,%7}, {%8,%9}, {%0,%1,%2,%3};" \
        : "+f"((d)[0]), "+f"((d)[1]), "+f"((d)[2]), "+f"((d)[3]) \
        : "r"((a)[0]), "r"((a)[1]), "r"((a)[2]), "r"((a)[3]), "r"(b0), "r"(b1))

__device__ __forceinline__ uint32_t smem_u32(const void* p) {
    uint32_t a;
    asm("{ .reg .u64 t; cvta.to.shared.u64 t, %1; cvt.u32.u64 %0, t; }" : "=r"(a) : "l"(p));
    return a;
}

__device__ __forceinline__ uint32_t pk_bf2(float a, float b, uint32_t& lo) {
    __nv_bfloat16 ha = __float2bfloat16(a), hb = __float2bfloat16(b);
    __nv_bfloat16 la = __float2bfloat16(a - __bfloat162float(ha));
    __nv_bfloat16 lb = __float2bfloat16(b - __bfloat162float(hb));
    lo = (uint32_t)__bfloat16_as_ushort(la) | ((uint32_t)__bfloat16_as_ushort(lb) << 16);
    return (uint32_t)__bfloat16_as_ushort(ha) | ((uint32_t)__bfloat16_as_ushort(hb) << 16);
}

// ---- precomputed bf16 hi/lo weights (row-major [n=128][k=128]); index 3 = Wo ----
__device__ __align__(16) __nv_bfloat16 g_WH[4][CCH * CCH];
__device__ __align__(16) __nv_bfloat16 g_WL[4][CCH * CCH];

__global__ void wsplit_kernel(const float* __restrict__ Wq,
                              const float* __restrict__ Wk,
                              const float* __restrict__ Wv,
                              const float* __restrict__ Wo)
{
    int i = blockIdx.x * blockDim.x + threadIdx.x;
    if (i >= 4 * CCH * CCH) return;
    int m = i / (CCH * CCH), e = i % (CCH * CCH);
    const float* W = (m == 0) ? Wq : (m == 1) ? Wk : (m == 2) ? Wv : Wo;
    float w = W[e];
    __nv_bfloat16 h = __float2bfloat16(w);
    g_WH[m][e] = h;
    g_WL[m][e] = __float2bfloat16(w - __bfloat162float(h));
}

// 128B-row ldmatrix addressing (validated)
__device__ __forceinline__ uint32_t a_addr(uint32_t base, int m0, int c2, int lane) {
    int sub = lane >> 3, rr = lane & 7;
    int row = m0 + ((sub & 1) << 3) + rr;
    int ch  = c2 + (sub >> 1);
    return base + row * 128 + (((ch ^ (row & 7)) & 7) << 4);
}
__device__ __forceinline__ uint32_t b_addr(uint32_t base, int n0, int c2, int lane) {
    int sub = lane >> 3, rr = lane & 7;
    int row = n0 + ((sub >> 1) << 3) + rr;
    int ch  = c2 + (sub & 1);
    return base + row * 128 + (((ch ^ (row & 7)) & 7) << 4);
}
// 64B-row ldmatrix addressing (validated)
__device__ __forceinline__ uint32_t a64_addr(uint32_t base, int m0, int c2, int lane) {
    int sub = lane >> 3, rr = lane & 7;
    int row = m0 + ((sub & 1) << 3) + rr;
    int ch  = c2 + (sub >> 1);
    return base + row * 64 + (((ch ^ ((row >> 1) & 3)) & 3) << 4);
}
__device__ __forceinline__ uint32_t b64_addr(uint32_t base, int n0, int c2, int lane) {
    int sub = lane >> 3, rr = lane & 7;
    int row = n0 + ((sub >> 1) << 3) + rr;
    int ch  = c2 + (sub & 1);
    return base + row * 64 + (((ch ^ ((row >> 1) & 3)) & 3) << 4);
}

__global__ __launch_bounds__(NT, 1)
void spatial_attn_kernel(const float* __restrict__ x,
                         const float* __restrict__ bq,
                         const float* __restrict__ bk,
                         const float* __restrict__ bv,
                         const float* __restrict__ bo,
                         float* __restrict__ out)
{
    extern __shared__ float sm[];
    char* smb = (char*)sm;
    const uint32_t smb0 = smem_u32(sm);
    const int t    = threadIdx.x;
    const int lane = t & 31;
    const int qg   = t >> 5;
    const int q0   = qg * ROWS;
    const size_t gbase = (size_t)blockIdx.x * (TT * CCH);
    const float* xg = x + gbase;
    float* yg = out + gbase;

    // warp MMA tile for QKV / Wo MMAs: 2 m-groups (48 rows) x 8 n-groups (16 cols)
    const int m0w = (qg & 1) * 48;
    const int n0w = (qg >> 1) * 16;

    // ======== phase A: QKV via mma.sync bf16 split (validated) ========
#pragma unroll 1
    for (int m = 0; m < 3; ++m) {
        float acc[3][2][4];
#pragma unroll
        for (int i = 0; i < 3; ++i)
#pragma unroll
            for (int j = 0; j < 2; ++j)
#pragma unroll
                for (int c = 0; c < 4; ++c) acc[i][j][c] = 0.f;

#pragma unroll 1
        for (int kh = 0; kh < 2; ++kh) {
            if (t < 384) {
                const int row = t >> 2, g = t & 3;
                const float4* src = (const float4*)xg + row * 32 + kh * 16 + g * 4;
                float4 f0 = src[0], f1 = src[1], f2 = src[2], f3 = src[3];
                uint4 h0, l0, h1, l1;
                h0.x = pk_bf2(f0.x, f0.y, l0.x); h0.y = pk_bf2(f0.z, f0.w, l0.y);
                h0.z = pk_bf2(f1.x, f1.y, l0.z); h0.w = pk_bf2(f1.z, f1.w, l0.w);
                h1.x = pk_bf2(f2.x, f2.y, l1.x); h1.y = pk_bf2(f2.z, f2.w, l1.y);
                h1.z = pk_bf2(f3.x, f3.y, l1.z); h1.w = pk_bf2(f3.z, f3.w, l1.w);
                const int c0 = (2 * g) ^ (row & 7);
                const int c1 = (2 * g + 1) ^ (row & 7);
                *(uint4*)(smb + XH_B + row * 128 + c0 * 16) = h0;
                *(uint4*)(smb + XH_B + row * 128 + c1 * 16) = h1;
                *(uint4*)(smb + XL_B + row * 128 + c0 * 16) = l0;
                *(uint4*)(smb + XL_B + row * 128 + c1 * 16) = l1;
            }
            {
                const int n = t >> 2;
                const int cb = (t & 3) * 2;
#pragma unroll
                for (int q = 0; q < 2; ++q) {
                    const int cl = cb + q;
                    const int swc = (cl ^ (n & 7)) & 7;
                    uint4 vh = *(const uint4*)((const char*)g_WH[m] + n * 256 + kh * 128 + cl * 16);
                    uint4 vl = *(const uint4*)((const char*)g_WL[m] + n * 256 + kh * 128 + cl * 16);
                    *(uint4*)(smb + WH_B + n * 128 + swc * 16) = vh;
                    *(uint4*)(smb + WL_B + n * 128 + swc * 16) = vl;
                }
            }
            __syncthreads();

#pragma unroll
            for (int kk = 0; kk < 4; ++kk) {
                const int c2 = 2 * kk;
                uint32_t Ah[3][4], Al[3][4], Bh[4], Bl[4];
#pragma unroll
                for (int i = 0; i < 3; ++i) {
                    LDSM4(Ah[i][0], Ah[i][1], Ah[i][2], Ah[i][3],
                          a_addr(smb0 + XH_B, m0w + 16 * i, c2, lane));
                    LDSM4(Al[i][0], Al[i][1], Al[i][2], Al[i][3],
                          a_addr(smb0 + XL_B, m0w + 16 * i, c2, lane));
                }
                LDSM4(Bh[0], Bh[1], Bh[2], Bh[3], b_addr(smb0 + WH_B, n0w, c2, lane));
                LDSM4(Bl[0], Bl[1], Bl[2], Bl[3], b_addr(smb0 + WL_B, n0w, c2, lane));
#pragma unroll
                for (int i = 0; i < 3; ++i)
#pragma unroll
                    for (int j = 0; j < 2; ++j) {
                        MMA16816(acc[i][j], Ah[i], Bh[2 * j], Bh[2 * j + 1]);
                        MMA16816(acc[i][j], Ah[i], Bl[2 * j], Bl[2 * j + 1]);
                        MMA16816(acc[i][j], Al[i], Bh[2 * j], Bh[2 * j + 1]);
                    }
            }
            __syncthreads();
        }

        if (m < 2) {
            // Q / K: fp32 for the FFMA2 QK^T
            const float* bias = (m == 0) ? bq : bk;
            const int off = (m == 0) ? OFF_Q : OFF_K;
#pragma unroll
            for (int j = 0; j < 2; ++j) {
                const int jc = n0w + 8 * j + 2 * (lane & 3);
                const float2 bb = *(const float2*)(bias + jc);
#pragma unroll
                for (int i = 0; i < 3; ++i) {
                    const int r = m0w + 16 * i + (lane >> 2);
                    float2 v0, v1;
                    v0.x = acc[i][j][0] + bb.x; v0.y = acc[i][j][1] + bb.y;
                    v1.x = acc[i][j][2] + bb.x; v1.y = acc[i][j][3] + bb.y;
                    *(float2*)(sm + off + r * LDA + jc)       = v0;
                    *(float2*)(sm + off + (r + 8) * LDA + jc) = v1;
                }
            }
        } else {
            // V: bf16 hi/lo into swizzled 256B-row [k][d] tiles (for A*V MMA B-operand)
#pragma unroll
            for (int j = 0; j < 2; ++j) {
                const int jc = n0w + 8 * j + 2 * (lane & 3);
                const float2 bb = *(const float2*)(bv + jc);
#pragma unroll
                for (int i = 0; i < 3; ++i) {
                    const int r = m0w + 16 * i + (lane >> 2);
#pragma unroll
                    for (int e = 0; e < 2; ++e) {
                        const int rr = r + 8 * e;
                        float vx = acc[i][j][2 * e + 0] + bb.x;
                        float vy = acc[i][j][2 * e + 1] + bb.y;
                        uint32_t lo; uint32_t hi = pk_bf2(vx, vy, lo);
                        const int chb = jc >> 3;
                        const int ch  = (chb & 8) | ((chb ^ (rr & 7)) & 7);
                        const int off = rr * 256 + ch * 16 + (jc & 7) * 2;
                        *(uint32_t*)(smb + VH_B + off) = hi;
                        *(uint32_t*)(smb + VL_B + off) = lo;
                    }
                }
            }
        }
    }
    __syncthreads();   // Q/K fp32 + V bf16 ready

    // ======== phase B ========
    const float scale = 0.17677669529663687f;  // 1/sqrt(32)
    float accy[3][2][4];
#pragma unroll
    for (int i = 0; i < 3; ++i)
#pragma unroll
        for (int j = 0; j < 2; ++j)
#pragma unroll
            for (int c = 0; c < 4; ++c) accy[i][j][c] = 0.f;

    // A*V warp tiling: 12 warps cover 96q x 32d (6 m-tiles x 2 n-tiles of 16)
    const int avm = qg % 6;            // q-tile
    const int avn = qg / 6;            // d-tile (valid when qg < 12)
    const int q0m = avm * 16;

#pragma unroll 1
    for (int h = 0; h < NH; ++h) {
        const int hc = h * HDIM;

        // ---- S_T[k][q] = scale * (Q[q,hc:] . K[k,hc:])  (FFMA2) ----
        {
            u64x acc2[ROWS][3];
#pragma unroll
            for (int i = 0; i < ROWS; ++i)
#pragma unroll
                for (int j = 0; j < 3; ++j) acc2[i][j] = 0ull;
            const int kb = lane * 3;
#pragma unroll
            for (int c4 = 0; c4 < 8; ++c4) {
                ulonglong2 qv[ROWS];
#pragma unroll
                for (int i = 0; i < ROWS; ++i)
                    qv[i] = *(const ulonglong2*)(sm + OFF_Q + (q0 + i) * LDA + hc + c4 * 4);
#pragma unroll
                for (int j = 0; j < 3; ++j) {
                    ulonglong2 kv = *(const ulonglong2*)(sm + OFF_K + (kb + j) * LDA + hc + c4 * 4);
#pragma unroll
                    for (int i = 0; i < ROWS; ++i) {
                        FMA2(acc2[i][j], qv[i].x, kv.x);
                        FMA2(acc2[i][j], qv[i].y, kv.y);
                    }
                }
            }
#pragma unroll
            for (int j = 0; j < 3; ++j)
#pragma unroll
                for (int i = 0; i < ROWS; ++i) {
                    float lo, hi; UNPK(lo, hi, acc2[i][j]);
                    sm[OFF_S + (kb + j) * LDSS + q0 + i] = (lo + hi) * scale;
                }
        }
        __syncthreads();

        // ---- softmax over q (axis=-2); write A directly as bf16 hi/lo ----
        {
#pragma unroll
            for (int r = 0; r < ROWS; ++r) {
                const int k = qg * ROWS + r;
                float v0 = sm[OFF_S + k * LDSS + lane];
                float v1 = sm[OFF_S + k * LDSS + lane + 32];
                float v2 = sm[OFF_S + k * LDSS + lane + 64];
                float mx = fmaxf(v0, fmaxf(v1, v2));
#pragma unroll
                for (int o = 16; o; o >>= 1) mx = fmaxf(mx, __shfl_xor_sync(0xffffffffu, mx, o));
                float e0 = __expf(v0 - mx), e1 = __expf(v1 - mx), e2 = __expf(v2 - mx);
                float s = e0 + e1 + e2;
#pragma unroll
                for (int o = 16; o; o >>= 1) s += __shfl_xor_sync(0xffffffffu, s, o);
                const float inv = 1.f / s;
                const float a0 = e0 * inv, a1 = e1 * inv, a2 = e2 * inv;
                // q = lane (plane0)
                {
                    __nv_bfloat16 bh = __float2bfloat16(a0);
                    __nv_bfloat16 bl = __float2bfloat16(a0 - __bfloat162float(bh));
                    const int ch  = ((lane >> 3) ^ (k & 7)) & 7;
                    const int off = k * 128 + ch * 16 + (lane & 7) * 2;
                    *(__nv_bfloat16*)(smb + AH0_B + off) = bh;
                    *(__nv_bfloat16*)(smb + AL0_B + off) = bl;
                }
                // q = lane + 32 (plane0)
                {
                    __nv_bfloat16 bh = __float2bfloat16(a1);
                    __nv_bfloat16 bl = __float2bfloat16(a1 - __bfloat162float(bh));
                    const int ch  = (((lane >> 3) + 4) ^ (k & 7)) & 7;
                    const int off = k * 128 + ch * 16 + (lane & 7) * 2;
                    *(__nv_bfloat16*)(smb + AH0_B + off) = bh;
                    *(__nv_bfloat16*)(smb + AL0_B + off) = bl;
                }
                // q = lane + 64 (plane1, 64B rows)
                {
                    __nv_bfloat16 bh = __float2bfloat16(a2);
                    __nv_bfloat16 bl = __float2bfloat16(a2 - __bfloat162float(bh));
                    const int ch  = ((lane >> 3) ^ ((k >> 1) & 3)) & 3;
                    const int off = k * 64 + ch * 16 + (lane & 7) * 2;
                    *(__nv_bfloat16*)(smb + AH1_B + off) = bh;
                    *(__nv_bfloat16*)(smb + AL1_B + off) = bl;
                }
            }
        }
        __syncthreads();

        // ---- A*V via mma.sync (12 warps): O[q][d] = sum_k A[k][q] * V[k][hc+d] ----
        float acco[2][4];
#pragma unroll
        for (int j = 0; j < 2; ++j)
#pragma unroll
            for (int c = 0; c < 4; ++c) acco[j][c] = 0.f;
        if (qg < 12) {
            const int n0 = hc + avn * 16;   // absolute V column
#pragma unroll
            for (int ks = 0; ks < 6; ++ks) {
                const int k0 = ks * 16;
                // A operand (trans from [k][q]): lanes -> krow = k0+(L&7)+8*(L>>4),
                // q-chunk = base + (L>>3)&1
                uint32_t Afh[4], Afl[4], Bfh[4], Bfl[4];
                {
                    const int krA = k0 + (lane & 7) + 8 * (lane >> 4);
                    const int qch = ((q0m & 63) >> 3) + ((lane >> 3) & 1);
                    uint32_t aoff, hB, lB;
                    if (q0m < 64) {
                        aoff = (uint32_t)(krA * 128 + (((qch ^ (krA & 7)) & 7) << 4));
                        hB = AH0_B; lB = AL0_B;
                    } else {
                        aoff = (uint32_t)(krA * 64 + (((qch ^ ((krA >> 1) & 3)) & 3) << 4));
                        hB = AH1_B; lB = AL1_B;
                    }
                    LDSM4T(Afh[0], Afh[1], Afh[2], Afh[3], smb0 + hB + aoff);
                    LDSM4T(Afl[0], Afl[1], Afl[2], Afl[3], smb0 + lB + aoff);
                }
                // V operand (trans from [k][d] 256B rows): krow = k0+(L&7)+8*((L>>3)&1),
                // d-chunk = n0/8 + (L>>4)
                {
                    const int krV = k0 + (lane & 7) + 8 * ((lane >> 3) & 1);
                    const int dch = (n0 >> 3) + (lane >> 4);
                    const int ch  = (dch & 8) | ((dch ^ (krV & 7)) & 7);
                    const uint32_t voff = (uint32_t)(krV * 256 + ch * 16);
                    LDSM4T(Bfh[0], Bfh[1], Bfh[2], Bfh[3], smb0 + VH_B + voff);
                    LDSM4T(Bfl[0], Bfl[1], Bfl[2], Bfl[3], smb0 + VL_B + voff);
                }
#pragma unroll
                for (int j = 0; j < 2; ++j) {
                    MMA16816(acco[j], Afh, Bfh[2 * j], Bfh[2 * j + 1]);
                    MMA16816(acco[j], Afh, Bfl[2 * j], Bfl[2 * j + 1]);
                    MMA16816(acco[j], Afl, Bfh[2 * j], Bfh[2 * j + 1]);
                }
            }
        }
        __syncthreads();   // A fully consumed -> region reusable for O / Wo staging

        // ---- stage O frags (bf16 hi/lo, 64B rows) + Wo head-slice ----
        if (qg < 12) {
#pragma unroll
            for (int j = 0; j < 2; ++j) {
                const int dl = avn * 16 + 8 * j + 2 * (lane & 3);   // local d 0..31
#pragma unroll
                for (int e = 0; e < 2; ++e) {
                    const int q = q0m + (lane >> 2) + 8 * e;
                    uint32_t lo; uint32_t hi = pk_bf2(acco[j][2 * e], acco[j][2 * e + 1], lo);
                    const int ch  = ((dl >> 3) ^ ((q >> 1) & 3)) & 3;
                    const int off = q * 64 + ch * 16 + (dl & 7) * 2;
                    *(uint32_t*)(smb + OH_B + off) = hi;
                    *(uint32_t*)(smb + OL_B + off) = lo;
                }
            }
        }
        {
            const int n  = t >> 2;
            const int ch = t & 3;
            const int swc = (ch ^ ((n >> 1) & 3)) & 3;
            uint4 vh = *(const uint4*)((const char*)g_WH[3] + n * 256 + hc * 2 + ch * 16);
            uint4 vl = *(const uint4*)((const char*)g_WL[3] + n * 256 + hc * 2 + ch * 16);
            *(uint4*)(smb + WOH_B + n * 64 + swc * 16) = vh;
            *(uint4*)(smb + WOL_B + n * 64 + swc * 16) = vl;
        }
        __syncthreads();

        // ---- y += O_h @ Wo_h^T via mma.sync (validated) ----
        {
#pragma unroll
            for (int kk = 0; kk < 2; ++kk) {
                const int c2 = 2 * kk;
                uint32_t Ah2[3][4], Al2[3][4], Bh2[4], Bl2[4];
#pragma unroll
                for (int i = 0; i < 3; ++i) {
                    LDSM4(Ah2[i][0], Ah2[i][1], Ah2[i][2], Ah2[i][3],
                          a64_addr(smb0 + OH_B, m0w + 16 * i, c2, lane));
                    LDSM4(Al2[i][0], Al2[i][1], Al2[i][2], Al2[i][3],
                          a64_addr(smb0 + OL_B, m0w + 16 * i, c2, lane));
                }
                LDSM4(Bh2[0], Bh2[1], Bh2[2], Bh2[3], b64_addr(smb0 + WOH_B, n0w, c2, lane));
                LDSM4(Bl2[0], Bl2[1], Bl2[2], Bl2[3], b64_addr(smb0 + WOL_B, n0w, c2, lane));
#pragma unroll
                for (int i = 0; i < 3; ++i)
#pragma unroll
                    for (int j = 0; j < 2; ++j) {
                        MMA16816(accy[i][j], Ah2[i], Bh2[2 * j], Bh2[2 * j + 1]);
                        MMA16816(accy[i][j], Ah2[i], Bl2[2 * j], Bl2[2 * j + 1]);
                        MMA16816(accy[i][j], Al2[i], Bh2[2 * j], Bh2[2 * j + 1]);
                    }
            }
        }
        __syncthreads();   // staging region reused by next head
    }

    // ---- epilogue: y = accy fragments + bo -> global ----
    {
#pragma unroll
        for (int j = 0; j < 2; ++j) {
            const int jc = n0w + 8 * j + 2 * (lane & 3);
            const float2 bb = *(const float2*)(bo + jc);
#pragma unroll
            for (int i = 0; i < 3; ++i) {
                const int r = m0w + 16 * i + (lane >> 2);
                float2 v0, v1;
                v0.x = accy[i][j][0] + bb.x; v0.y = accy[i][j][1] + bb.y;
                v1.x = accy[i][j][2] + bb.x; v1.y = accy[i][j][3] + bb.y;
                *(float2*)(yg + r * CCH + jc)       = v0;
                *(float2*)(yg + (r + 8) * CCH + jc) = v1;
            }
        }
    }
}

extern "C" void kernel_launch(void* const* d_in, const int* in_sizes, int n_in,
                              void* d_out, int out_size)
{
    const float* x  = (const float*)d_in[0];
    const float* Wq = (const float*)d_in[1];
    const float* bq = (const float*)d_in[2];
    const float* Wk = (const float*)d_in[3];
    const float* bk = (const float*)d_in[4];
    const float* Wv = (const float*)d_in[5];
    const float* bv = (const float*)d_in[6];
    const float* Wo = (const float*)d_in[7];
    const float* bo = (const float*)d_in[8];
    float* y = (float*)d_out;

    const int nodes = in_sizes[0] / (TT * CCH);   // 4096

    wsplit_kernel<<<(4 * CCH * CCH + 255) / 256, 256>>>(Wq, Wk, Wv, Wo);

    cudaFuncSetAttribute(spatial_attn_kernel,
                         cudaFuncAttributeMaxDynamicSharedMemorySize, SMEM_BYTES);
    spatial_attn_kernel<<<nodes, NT, SMEM_BYTES>>>(x, bq, bk, bv, bo, y);
}

// round 15
// speedup vs baseline: 1.7774x; 1.0764x over previous
#include <cuda_runtime.h>
#include <cuda_bf16.h>
#include <cstdint>

// SpatialAttention fused kernel, round 15:
//  - ALL four GEMMs on mma.sync bf16 hi/lo compensated split (fp32 accum):
//    QKV proj (validated), QK^T (new: S_T = K.Q^T, 256B-row tiles, non-trans ldmatrix),
//    A*V (validated, trans ldmatrix), Wo proj (validated).
//  - Query-axis softmax stays fp32/shuffle (validated); writes A directly as bf16 hi/lo.
// One CTA (512 thr) per node.

#define TT 96
#define CCH 128
#define NH 4
#define HDIM 32
#define LDSS 98
#define NT 512
#define ROWS 6

// ---- byte offsets: persistent bf16 tiles (96 rows x 256B, swizzled) ----
#define QH_B 0
#define QL_B 24576
#define KH_B 49152
#define KL_B 73728
#define VH_B 98304
#define VL_B 122880
// ---- S fp32 (96 x 98 floats) ----
#define OFF_S 36864              // float index; bytes [147456, 185088)
// ---- A planes (bf16 hi/lo; q<64: 128B rows, q>=64: 64B rows) ----
#define AH0_B 185088             // 96x128B
#define AH1_B 197376             // 96x64B
#define AL0_B 203520
#define AL1_B 215808             // ends 221952
#define SMEM_BYTES 221952
// ---- phase-A staging (overlaps S+A regions, dead during phase A) ----
#define XH_B 147456              // 96x128B
#define XL_B 159744
#define WH_B 172032              // 128x128B
#define WL_B 188416              // ends 204800
// ---- Wo staging (overlaps A region, after A consumed) ----
#define OH_B  185088             // 96x64B
#define OL_B  191232
#define WOH_B 197376             // 128x64B
#define WOL_B 205568             // ends 213760

#define LDSM4(r0, r1, r2, r3, a) \
    asm volatile("ldmatrix.sync.aligned.m8n8.x4.shared.b16 {%0,%1,%2,%3}, [%4];" \
        : "=r"(r0), "=r"(r1), "=r"(r2), "=r"(r3) : "r"(a))
#define LDSM4T(r0, r1, r2, r3, a) \
    asm volatile("ldmatrix.sync.aligned.m8n8.x4.trans.shared.b16 {%0,%1,%2,%3}, [%4];" \
        : "=r"(r0), "=r"(r1), "=r"(r2), "=r"(r3) : "r"(a))

#define MMA16816(d, a, b0, b1) \
    asm volatile("mma.sync.aligned.m16n8k16.row.col.f32.bf16.bf16.f32 " \
        "{%0,%1,%2,%3}, {%4,%5,%6,%7}, {%8,%9}, {%0,%1,%2,%3};" \
        : "+f"((d)[0]), "+f"((d)[1]), "+f"((d)[2]), "+f"((d)[3]) \
        : "r"((a)[0]), "r"((a)[1]), "r"((a)[2]), "r"((a)[3]), "r"(b0), "r"(b1))

__device__ __forceinline__ uint32_t smem_u32(const void* p) {
    uint32_t a;
    asm("{ .reg .u64 t; cvta.to.shared.u64 t, %1; cvt.u32.u64 %0, t; }" : "=r"(a) : "l"(p));
    return a;
}

__device__ __forceinline__ uint32_t pk_bf2(float a, float b, uint32_t& lo) {
    __nv_bfloat16 ha = __float2bfloat16(a), hb = __float2bfloat16(b);
    __nv_bfloat16 la = __float2bfloat16(a - __bfloat162float(ha));
    __nv_bfloat16 lb = __float2bfloat16(b - __bfloat162float(hb));
    lo = (uint32_t)__bfloat16_as_ushort(la) | ((uint32_t)__bfloat16_as_ushort(lb) << 16);
    return (uint32_t)__bfloat16_as_ushort(ha) | ((uint32_t)__bfloat16_as_ushort(hb) << 16);
}

// ---- precomputed bf16 hi/lo weights (row-major [n=128][k=128]); index 3 = Wo ----
__device__ __align__(16) __nv_bfloat16 g_WH[4][CCH * CCH];
__device__ __align__(16) __nv_bfloat16 g_WL[4][CCH * CCH];

__global__ void wsplit_kernel(const float* __restrict__ Wq,
                              const float* __restrict__ Wk,
                              const float* __restrict__ Wv,
                              const float* __restrict__ Wo)
{
    int i = blockIdx.x * blockDim.x + threadIdx.x;
    if (i >= 4 * CCH * CCH) return;
    int m = i / (CCH * CCH), e = i % (CCH * CCH);
    const float* W = (m == 0) ? Wq : (m == 1) ? Wk : (m == 2) ? Wv : Wo;
    float w = W[e];
    __nv_bfloat16 h = __float2bfloat16(w);
    g_WH[m][e] = h;
    g_WL[m][e] = __float2bfloat16(w - __bfloat162float(h));
}

// 128B-row ldmatrix addressing (validated)
__device__ __forceinline__ uint32_t a_addr(uint32_t base, int m0, int c2, int lane) {
    int sub = lane >> 3, rr = lane & 7;
    int row = m0 + ((sub & 1) << 3) + rr;
    int ch  = c2 + (sub >> 1);
    return base + row * 128 + (((ch ^ (row & 7)) & 7) << 4);
}
__device__ __forceinline__ uint32_t b_addr(uint32_t base, int n0, int c2, int lane) {
    int sub = lane >> 3, rr = lane & 7;
    int row = n0 + ((sub >> 1) << 3) + rr;
    int ch  = c2 + (sub & 1);
    return base + row * 128 + (((ch ^ (row & 7)) & 7) << 4);
}
// 64B-row ldmatrix addressing (validated)
__device__ __forceinline__ uint32_t a64_addr(uint32_t base, int m0, int c2, int lane) {
    int sub = lane >> 3, rr = lane & 7;
    int row = m0 + ((sub & 1) << 3) + rr;
    int ch  = c2 + (sub >> 1);
    return base + row * 64 + (((ch ^ ((row >> 1) & 3)) & 3) << 4);
}
__device__ __forceinline__ uint32_t b64_addr(uint32_t base, int n0, int c2, int lane) {
    int sub = lane >> 3, rr = lane & 7;
    int row = n0 + ((sub >> 1) << 3) + rr;
    int ch  = c2 + (sub & 1);
    return base + row * 64 + (((ch ^ ((row >> 1) & 3)) & 3) << 4);
}
// 256B-row ldmatrix addressing (matches the V/Q/K tile store swizzle)
__device__ __forceinline__ uint32_t t256_a(uint32_t base, int m0, int chb, int lane) {
    int sub = lane >> 3, rr = lane & 7;
    int row = m0 + ((sub & 1) << 3) + rr;
    int ch  = chb + (sub >> 1);
    int sw  = (ch & 8) | ((ch ^ (row & 7)) & 7);
    return base + row * 256 + sw * 16;
}
__device__ __forceinline__ uint32_t t256_b(uint32_t base, int n0, int chb, int lane) {
    int sub = lane >> 3, rr = lane & 7;
    int row = n0 + ((sub >> 1) << 3) + rr;
    int ch  = chb + (sub & 1);
    int sw  = (ch & 8) | ((ch ^ (row & 7)) & 7);
    return base + row * 256 + sw * 16;
}

__global__ __launch_bounds__(NT, 1)
void spatial_attn_kernel(const float* __restrict__ x,
                         const float* __restrict__ bq,
                         const float* __restrict__ bk,
                         const float* __restrict__ bv,
                         const float* __restrict__ bo,
                         float* __restrict__ out)
{
    extern __shared__ float sm[];
    char* smb = (char*)sm;
    const uint32_t smb0 = smem_u32(sm);
    const int t    = threadIdx.x;
    const int lane = t & 31;
    const int qg   = t >> 5;
    const size_t gbase = (size_t)blockIdx.x * (TT * CCH);
    const float* xg = x + gbase;
    float* yg = out + gbase;

    // warp MMA tile for QKV / Wo MMAs: 2 m-groups (48 rows) x 8 n-groups (16 cols)
    const int m0w = (qg & 1) * 48;
    const int n0w = (qg >> 1) * 16;

    // ======== phase A: QKV via mma.sync bf16 split -> bf16 hi/lo 256B-row tiles ========
#pragma unroll 1
    for (int m = 0; m < 3; ++m) {
        float acc[3][2][4];
#pragma unroll
        for (int i = 0; i < 3; ++i)
#pragma unroll
            for (int j = 0; j < 2; ++j)
#pragma unroll
                for (int c = 0; c < 4; ++c) acc[i][j][c] = 0.f;

#pragma unroll 1
        for (int kh = 0; kh < 2; ++kh) {
            if (t < 384) {
                const int row = t >> 2, g = t & 3;
                const float4* src = (const float4*)xg + row * 32 + kh * 16 + g * 4;
                float4 f0 = src[0], f1 = src[1], f2 = src[2], f3 = src[3];
                uint4 h0, l0, h1, l1;
                h0.x = pk_bf2(f0.x, f0.y, l0.x); h0.y = pk_bf2(f0.z, f0.w, l0.y);
                h0.z = pk_bf2(f1.x, f1.y, l0.z); h0.w = pk_bf2(f1.z, f1.w, l0.w);
                h1.x = pk_bf2(f2.x, f2.y, l1.x); h1.y = pk_bf2(f2.z, f2.w, l1.y);
                h1.z = pk_bf2(f3.x, f3.y, l1.z); h1.w = pk_bf2(f3.z, f3.w, l1.w);
                const int c0 = (2 * g) ^ (row & 7);
                const int c1 = (2 * g + 1) ^ (row & 7);
                *(uint4*)(smb + XH_B + row * 128 + c0 * 16) = h0;
                *(uint4*)(smb + XH_B + row * 128 + c1 * 16) = h1;
                *(uint4*)(smb + XL_B + row * 128 + c0 * 16) = l0;
                *(uint4*)(smb + XL_B + row * 128 + c1 * 16) = l1;
            }
            {
                const int n = t >> 2;
                const int cb = (t & 3) * 2;
#pragma unroll
                for (int q = 0; q < 2; ++q) {
                    const int cl = cb + q;
                    const int swc = (cl ^ (n & 7)) & 7;
                    uint4 vh = *(const uint4*)((const char*)g_WH[m] + n * 256 + kh * 128 + cl * 16);
                    uint4 vl = *(const uint4*)((const char*)g_WL[m] + n * 256 + kh * 128 + cl * 16);
                    *(uint4*)(smb + WH_B + n * 128 + swc * 16) = vh;
                    *(uint4*)(smb + WL_B + n * 128 + swc * 16) = vl;
                }
            }
            __syncthreads();

#pragma unroll
            for (int kk = 0; kk < 4; ++kk) {
                const int c2 = 2 * kk;
                uint32_t Ah[3][4], Al[3][4], Bh[4], Bl[4];
#pragma unroll
                for (int i = 0; i < 3; ++i) {
                    LDSM4(Ah[i][0], Ah[i][1], Ah[i][2], Ah[i][3],
                          a_addr(smb0 + XH_B, m0w + 16 * i, c2, lane));
                    LDSM4(Al[i][0], Al[i][1], Al[i][2], Al[i][3],
                          a_addr(smb0 + XL_B, m0w + 16 * i, c2, lane));
                }
                LDSM4(Bh[0], Bh[1], Bh[2], Bh[3], b_addr(smb0 + WH_B, n0w, c2, lane));
                LDSM4(Bl[0], Bl[1], Bl[2], Bl[3], b_addr(smb0 + WL_B, n0w, c2, lane));
#pragma unroll
                for (int i = 0; i < 3; ++i)
#pragma unroll
                    for (int j = 0; j < 2; ++j) {
                        MMA16816(acc[i][j], Ah[i], Bh[2 * j], Bh[2 * j + 1]);
                        MMA16816(acc[i][j], Ah[i], Bl[2 * j], Bl[2 * j + 1]);
                        MMA16816(acc[i][j], Al[i], Bh[2 * j], Bh[2 * j + 1]);
                    }
            }
            __syncthreads();
        }

        // epilogue: +bias, split to bf16 hi/lo, store into 256B-row swizzled tile
        {
            const float* bias = (m == 0) ? bq : (m == 1) ? bk : bv;
            const uint32_t hB = (m == 0) ? QH_B : (m == 1) ? KH_B : VH_B;
            const uint32_t lB = hB + 24576;
#pragma unroll
            for (int j = 0; j < 2; ++j) {
                const int jc = n0w + 8 * j + 2 * (lane & 3);
                const float2 bb = *(const float2*)(bias + jc);
#pragma unroll
                for (int i = 0; i < 3; ++i) {
                    const int r = m0w + 16 * i + (lane >> 2);
#pragma unroll
                    for (int e = 0; e < 2; ++e) {
                        const int rr = r + 8 * e;
                        float vx = acc[i][j][2 * e + 0] + bb.x;
                        float vy = acc[i][j][2 * e + 1] + bb.y;
                        uint32_t lo; uint32_t hi = pk_bf2(vx, vy, lo);
                        const int chb = jc >> 3;
                        const int ch  = (chb & 8) | ((chb ^ (rr & 7)) & 7);
                        const int off = rr * 256 + ch * 16 + (jc & 7) * 2;
                        *(uint32_t*)(smb + hB + off) = hi;
                        *(uint32_t*)(smb + lB + off) = lo;
                    }
                }
            }
        }
    }
    __syncthreads();   // Q/K/V bf16 tiles ready

    // ======== phase B ========
    const float scale = 0.17677669529663687f;  // 1/sqrt(32)
    float accy[3][2][4];
#pragma unroll
    for (int i = 0; i < 3; ++i)
#pragma unroll
        for (int j = 0; j < 2; ++j)
#pragma unroll
            for (int c = 0; c < 4; ++c) accy[i][j][c] = 0.f;

    // A*V warp tiling (12 warps): 96q x 32d
    const int avm = qg % 6;
    const int avn = qg / 6;
    const int q0m = avm * 16;

#pragma unroll 1
    for (int h = 0; h < NH; ++h) {
        const int hc = h * HDIM;
        const int chH = hc >> 3;   // base 8-col chunk of this head

        // ---- S_T = K . Q^T via mma.sync (12 warps: k-rows 2x48, q-cols 6x16) ----
        if (qg < 12) {
            const int km0 = (qg & 1) * 48;
            const int q0n = (qg >> 1) * 16;
            float accs[3][2][4];
#pragma unroll
            for (int i = 0; i < 3; ++i)
#pragma unroll
                for (int j = 0; j < 2; ++j)
#pragma unroll
                    for (int c = 0; c < 4; ++c) accs[i][j][c] = 0.f;
#pragma unroll
            for (int kk = 0; kk < 2; ++kk) {
                const int chb = chH + 2 * kk;
                uint32_t Kh[3][4], Kl[3][4], Qh[4], Ql[4];
#pragma unroll
                for (int i = 0; i < 3; ++i) {
                    LDSM4(Kh[i][0], Kh[i][1], Kh[i][2], Kh[i][3],
                          t256_a(smb0 + KH_B, km0 + 16 * i, chb, lane));
                    LDSM4(Kl[i][0], Kl[i][1], Kl[i][2], Kl[i][3],
                          t256_a(smb0 + KL_B, km0 + 16 * i, chb, lane));
                }
                LDSM4(Qh[0], Qh[1], Qh[2], Qh[3], t256_b(smb0 + QH_B, q0n, chb, lane));
                LDSM4(Ql[0], Ql[1], Ql[2], Ql[3], t256_b(smb0 + QL_B, q0n, chb, lane));
#pragma unroll
                for (int i = 0; i < 3; ++i)
#pragma unroll
                    for (int j = 0; j < 2; ++j) {
                        MMA16816(accs[i][j], Kh[i], Qh[2 * j], Qh[2 * j + 1]);
                        MMA16816(accs[i][j], Kh[i], Ql[2 * j], Ql[2 * j + 1]);
                        MMA16816(accs[i][j], Kl[i], Qh[2 * j], Qh[2 * j + 1]);
                    }
            }
            // store S_T fp32 (scaled)
#pragma unroll
            for (int j = 0; j < 2; ++j) {
                const int qc = q0n + 8 * j + 2 * (lane & 3);
#pragma unroll
                for (int i = 0; i < 3; ++i) {
                    const int kr = km0 + 16 * i + (lane >> 2);
                    float2 v0, v1;
                    v0.x = accs[i][j][0] * scale; v0.y = accs[i][j][1] * scale;
                    v1.x = accs[i][j][2] * scale; v1.y = accs[i][j][3] * scale;
                    *(float2*)(sm + OFF_S + kr * LDSS + qc)       = v0;
                    *(float2*)(sm + OFF_S + (kr + 8) * LDSS + qc) = v1;
                }
            }
        }
        __syncthreads();

        // ---- softmax over q (axis=-2); write A directly as bf16 hi/lo ----
        {
#pragma unroll
            for (int r = 0; r < ROWS; ++r) {
                const int k = qg * ROWS + r;
                float v0 = sm[OFF_S + k * LDSS + lane];
                float v1 = sm[OFF_S + k * LDSS + lane + 32];
                float v2 = sm[OFF_S + k * LDSS + lane + 64];
                float mx = fmaxf(v0, fmaxf(v1, v2));
#pragma unroll
                for (int o = 16; o; o >>= 1) mx = fmaxf(mx, __shfl_xor_sync(0xffffffffu, mx, o));
                float e0 = __expf(v0 - mx), e1 = __expf(v1 - mx), e2 = __expf(v2 - mx);
                float s = e0 + e1 + e2;
#pragma unroll
                for (int o = 16; o; o >>= 1) s += __shfl_xor_sync(0xffffffffu, s, o);
                const float inv = 1.f / s;
                const float a0 = e0 * inv, a1 = e1 * inv, a2 = e2 * inv;
                {
                    __nv_bfloat16 bh = __float2bfloat16(a0);
                    __nv_bfloat16 bl = __float2bfloat16(a0 - __bfloat162float(bh));
                    const int ch  = ((lane >> 3) ^ (k & 7)) & 7;
                    const int off = k * 128 + ch * 16 + (lane & 7) * 2;
                    *(__nv_bfloat16*)(smb + AH0_B + off) = bh;
                    *(__nv_bfloat16*)(smb + AL0_B + off) = bl;
                }
                {
                    __nv_bfloat16 bh = __float2bfloat16(a1);
                    __nv_bfloat16 bl = __float2bfloat16(a1 - __bfloat162float(bh));
                    const int ch  = (((lane >> 3) + 4) ^ (k & 7)) & 7;
                    const int off = k * 128 + ch * 16 + (lane & 7) * 2;
                    *(__nv_bfloat16*)(smb + AH0_B + off) = bh;
                    *(__nv_bfloat16*)(smb + AL0_B + off) = bl;
                }
                {
                    __nv_bfloat16 bh = __float2bfloat16(a2);
                    __nv_bfloat16 bl = __float2bfloat16(a2 - __bfloat162float(bh));
                    const int ch  = ((lane >> 3) ^ ((k >> 1) & 3)) & 3;
                    const int off = k * 64 + ch * 16 + (lane & 7) * 2;
                    *(__nv_bfloat16*)(smb + AH1_B + off) = bh;
                    *(__nv_bfloat16*)(smb + AL1_B + off) = bl;
                }
            }
        }
        __syncthreads();

        // ---- A*V via mma.sync (12 warps, trans ldmatrix; validated) ----
        float acco[2][4];
#pragma unroll
        for (int j = 0; j < 2; ++j)
#pragma unroll
            for (int c = 0; c < 4; ++c) acco[j][c] = 0.f;
        if (qg < 12) {
            const int n0 = hc + avn * 16;
#pragma unroll
            for (int ks = 0; ks < 6; ++ks) {
                const int k0 = ks * 16;
                uint32_t Afh[4], Afl[4], Bfh[4], Bfl[4];
                {
                    const int krA = k0 + (lane & 7) + 8 * (lane >> 4);
                    const int qch = ((q0m & 63) >> 3) + ((lane >> 3) & 1);
                    uint32_t aoff, hB, lB;
                    if (q0m < 64) {
                        aoff = (uint32_t)(krA * 128 + (((qch ^ (krA & 7)) & 7) << 4));
                        hB = AH0_B; lB = AL0_B;
                    } else {
                        aoff = (uint32_t)(krA * 64 + (((qch ^ ((krA >> 1) & 3)) & 3) << 4));
                        hB = AH1_B; lB = AL1_B;
                    }
                    LDSM4T(Afh[0], Afh[1], Afh[2], Afh[3], smb0 + hB + aoff);
                    LDSM4T(Afl[0], Afl[1], Afl[2], Afl[3], smb0 + lB + aoff);
                }
                {
                    const int krV = k0 + (lane & 7) + 8 * ((lane >> 3) & 1);
                    const int dch = (n0 >> 3) + (lane >> 4);
                    const int ch  = (dch & 8) | ((dch ^ (krV & 7)) & 7);
                    const uint32_t voff = (uint32_t)(krV * 256 + ch * 16);
                    LDSM4T(Bfh[0], Bfh[1], Bfh[2], Bfh[3], smb0 + VH_B + voff);
                    LDSM4T(Bfl[0], Bfl[1], Bfl[2], Bfl[3], smb0 + VL_B + voff);
                }
#pragma unroll
                for (int j = 0; j < 2; ++j) {
                    MMA16816(acco[j], Afh, Bfh[2 * j], Bfh[2 * j + 1]);
                    MMA16816(acco[j], Afh, Bfl[2 * j], Bfl[2 * j + 1]);
                    MMA16816(acco[j], Afl, Bfh[2 * j], Bfh[2 * j + 1]);
                }
            }
        }
        __syncthreads();   // A consumed -> region reusable

        // ---- stage O frags (bf16 hi/lo, 64B rows) + Wo head-slice ----
        if (qg < 12) {
#pragma unroll
            for (int j = 0; j < 2; ++j) {
                const int dl = avn * 16 + 8 * j + 2 * (lane & 3);
#pragma unroll
                for (int e = 0; e < 2; ++e) {
                    const int q = q0m + (lane >> 2) + 8 * e;
                    uint32_t lo; uint32_t hi = pk_bf2(acco[j][2 * e], acco[j][2 * e + 1], lo);
                    const int ch  = ((dl >> 3) ^ ((q >> 1) & 3)) & 3;
                    const int off = q * 64 + ch * 16 + (dl & 7) * 2;
                    *(uint32_t*)(smb + OH_B + off) = hi;
                    *(uint32_t*)(smb + OL_B + off) = lo;
                }
            }
        }
        {
            const int n  = t >> 2;
            const int ch = t & 3;
            const int swc = (ch ^ ((n >> 1) & 3)) & 3;
            uint4 vh = *(const uint4*)((const char*)g_WH[3] + n * 256 + hc * 2 + ch * 16);
            uint4 vl = *(const uint4*)((const char*)g_WL[3] + n * 256 + hc * 2 + ch * 16);
            *(uint4*)(smb + WOH_B + n * 64 + swc * 16) = vh;
            *(uint4*)(smb + WOL_B + n * 64 + swc * 16) = vl;
        }
        __syncthreads();

        // ---- y += O_h @ Wo_h^T via mma.sync (validated) ----
        {
#pragma unroll
            for (int kk = 0; kk < 2; ++kk) {
                const int c2 = 2 * kk;
                uint32_t Ah2[3][4], Al2[3][4], Bh2[4], Bl2[4];
#pragma unroll
                for (int i = 0; i < 3; ++i) {
                    LDSM4(Ah2[i][0], Ah2[i][1], Ah2[i][2], Ah2[i][3],
                          a64_addr(smb0 + OH_B, m0w + 16 * i, c2, lane));
                    LDSM4(Al2[i][0], Al2[i][1], Al2[i][2], Al2[i][3],
                          a64_addr(smb0 + OL_B, m0w + 16 * i, c2, lane));
                }
                LDSM4(Bh2[0], Bh2[1], Bh2[2], Bh2[3], b64_addr(smb0 + WOH_B, n0w, c2, lane));
                LDSM4(Bl2[0], Bl2[1], Bl2[2], Bl2[3], b64_addr(smb0 + WOL_B, n0w, c2, lane));
#pragma unroll
                for (int i = 0; i < 3; ++i)
#pragma unroll
                    for (int j = 0; j < 2; ++j) {
                        MMA16816(accy[i][j], Ah2[i], Bh2[2 * j], Bh2[2 * j + 1]);
                        MMA16816(accy[i][j], Ah2[i], Bl2[2 * j], Bl2[2 * j + 1]);
                        MMA16816(accy[i][j], Al2[i], Bh2[2 * j], Bh2[2 * j + 1]);
                    }
            }
        }
        __syncthreads();
    }

    // ---- epilogue: y = accy fragments + bo -> global ----
    {
#pragma unroll
        for (int j = 0; j < 2; ++j) {
            const int jc = n0w + 8 * j + 2 * (lane & 3);
            const float2 bb = *(const float2*)(bo + jc);
#pragma unroll
            for (int i = 0; i < 3; ++i) {
                const int r = m0w + 16 * i + (lane >> 2);
                float2 v0, v1;
                v0.x = accy[i][j][0] + bb.x; v0.y = accy[i][j][1] + bb.y;
                v1.x = accy[i][j][2] + bb.x; v1.y = accy[i][j][3] + bb.y;
                *(float2*)(yg + r * CCH + jc)       = v0;
                *(float2*)(yg + (r + 8) * CCH + jc) = v1;
            }
        }
    }
}

extern "C" void kernel_launch(void* const* d_in, const int* in_sizes, int n_in,
                              void* d_out, int out_size)
{
    const float* x  = (const float*)d_in[0];
    const float* Wq = (const float*)d_in[1];
    const float* bq = (const float*)d_in[2];
    const float* Wk = (const float*)d_in[3];
    const float* bk = (const float*)d_in[4];
    const float* Wv = (const float*)d_in[5];
    const float* bv = (const float*)d_in[6];
    const float* Wo = (const float*)d_in[7];
    const float* bo = (const float*)d_in[8];
    float* y = (float*)d_out;

    const int nodes = in_sizes[0] / (TT * CCH);   // 4096

    wsplit_kernel<<<(4 * CCH * CCH + 255) / 256, 256>>>(Wq, Wk, Wv, Wo);

    cudaFuncSetAttribute(spatial_attn_kernel,
                         cudaFuncAttributeMaxDynamicSharedMemorySize, SMEM_BYTES);
    spatial_attn_kernel<<<nodes, NT, SMEM_BYTES>>>(x, bq, bk, bv, bo, y);
}

// round 16
// speedup vs baseline: 1.8048x; 1.0154x over previous
#include <cuda_runtime.h>
#include <cuda_bf16.h>
#include <cstdint>

// SpatialAttention fused kernel, round 16:
//  - ALL four GEMMs on mma.sync bf16 hi/lo compensated split (fp32 accum)  [validated]
//  - NEW: X staged ONCE into 256B-row bf16 hi/lo tiles (phase A reads via t256_a);
//         Wo staging done by idle warps 12-15 concurrently with A*V; O/WO staging in
//         dead S region; 4 barriers/head instead of 5.
// One CTA (512 thr) per node.

#define TT 96
#define CCH 128
#define NH 4
#define HDIM 32
#define LDSS 98
#define NT 512
#define ROWS 6

// ---- byte offsets: persistent bf16 tiles (96 rows x 256B, swizzled) ----
#define QH_B 0
#define QL_B 24576
#define KH_B 49152
#define KL_B 73728
#define VH_B 98304
#define VL_B 122880
// ---- S fp32 (96 x 98 floats), bytes [147456, 185088) ----
#define OFF_S 36864
// ---- A planes (bf16 hi/lo; q<64: 128B rows, q>=64: 64B rows) ----
#define AH0_B 185088             // 96x128B
#define AH1_B 197376             // 96x64B
#define AL0_B 203520
#define AL1_B 215808             // ends 221952
// ---- phase-A staging (time-disjoint with S/A regions) ----
#define XH2_B 147456             // X hi: 96x256B (staged ONCE)
#define XL2_B 172032             // X lo            ends 196608
#define WH_B  196608             // W slab hi: 128x128B (per m,kh)
#define WL_B  212992             // W slab lo       ends 229376
#define SMEM_BYTES 229376
// ---- Wo staging (phase B, inside dead S region) ----
#define OH_B  147456             // 96x64B
#define OL_B  153600
#define WOH_B 159744             // 128x64B
#define WOL_B 167936             // ends 176128 (< 185088)

#define LDSM4(r0, r1, r2, r3, a) \
    asm volatile("ldmatrix.sync.aligned.m8n8.x4.shared.b16 {%0,%1,%2,%3}, [%4];" \
        : "=r"(r0), "=r"(r1), "=r"(r2), "=r"(r3) : "r"(a))
#define LDSM4T(r0, r1, r2, r3, a) \
    asm volatile("ldmatrix.sync.aligned.m8n8.x4.trans.shared.b16 {%0,%1,%2,%3}, [%4];" \
        : "=r"(r0), "=r"(r1), "=r"(r2), "=r"(r3) : "r"(a))

#define MMA16816(d, a, b0, b1) \
    asm volatile("mma.sync.aligned.m16n8k16.row.col.f32.bf16.bf16.f32 " \
        "{%0,%1,%2,%3}, {%4,%5,%6,%7}, {%8,%9}, {%0,%1,%2,%3};" \
        : "+f"((d)[0]), "+f"((d)[1]), "+f"((d)[2]), "+f"((d)[3]) \
        : "r"((a)[0]), "r"((a)[1]), "r"((a)[2]), "r"((a)[3]), "r"(b0), "r"(b1))

__device__ __forceinline__ uint32_t smem_u32(const void* p) {
    uint32_t a;
    asm("{ .reg .u64 t; cvta.to.shared.u64 t, %1; cvt.u32.u64 %0, t; }" : "=r"(a) : "l"(p));
    return a;
}

__device__ __forceinline__ uint32_t pk_bf2(float a, float b, uint32_t& lo) {
    __nv_bfloat16 ha = __float2bfloat16(a), hb = __float2bfloat16(b);
    __nv_bfloat16 la = __float2bfloat16(a - __bfloat162float(ha));
    __nv_bfloat16 lb = __float2bfloat16(b - __bfloat162float(hb));
    lo = (uint32_t)__bfloat16_as_ushort(la) | ((uint32_t)__bfloat16_as_ushort(lb) << 16);
    return (uint32_t)__bfloat16_as_ushort(ha) | ((uint32_t)__bfloat16_as_ushort(hb) << 16);
}

// ---- precomputed bf16 hi/lo weights (row-major [n=128][k=128]); index 3 = Wo ----
__device__ __align__(16) __nv_bfloat16 g_WH[4][CCH * CCH];
__device__ __align__(16) __nv_bfloat16 g_WL[4][CCH * CCH];

__global__ void wsplit_kernel(const float* __restrict__ Wq,
                              const float* __restrict__ Wk,
                              const float* __restrict__ Wv,
                              const float* __restrict__ Wo)
{
    int i = blockIdx.x * blockDim.x + threadIdx.x;
    if (i >= 4 * CCH * CCH) return;
    int m = i / (CCH * CCH), e = i % (CCH * CCH);
    const float* W = (m == 0) ? Wq : (m == 1) ? Wk : (m == 2) ? Wv : Wo;
    float w = W[e];
    __nv_bfloat16 h = __float2bfloat16(w);
    g_WH[m][e] = h;
    g_WL[m][e] = __float2bfloat16(w - __bfloat162float(h));
}

// 128B-row ldmatrix addressing for the W slab (validated)
__device__ __forceinline__ uint32_t b_addr(uint32_t base, int n0, int c2, int lane) {
    int sub = lane >> 3, rr = lane & 7;
    int row = n0 + ((sub >> 1) << 3) + rr;
    int ch  = c2 + (sub & 1);
    return base + row * 128 + (((ch ^ (row & 7)) & 7) << 4);
}
// 64B-row ldmatrix addressing (validated)
__device__ __forceinline__ uint32_t a64_addr(uint32_t base, int m0, int c2, int lane) {
    int sub = lane >> 3, rr = lane & 7;
    int row = m0 + ((sub & 1) << 3) + rr;
    int ch  = c2 + (sub >> 1);
    return base + row * 64 + (((ch ^ ((row >> 1) & 3)) & 3) << 4);
}
__device__ __forceinline__ uint32_t b64_addr(uint32_t base, int n0, int c2, int lane) {
    int sub = lane >> 3, rr = lane & 7;
    int row = n0 + ((sub >> 1) << 3) + rr;
    int ch  = c2 + (sub & 1);
    return base + row * 64 + (((ch ^ ((row >> 1) & 3)) & 3) << 4);
}
// 256B-row ldmatrix addressing (matches the X/Q/K/V tile store swizzle; validated)
__device__ __forceinline__ uint32_t t256_a(uint32_t base, int m0, int chb, int lane) {
    int sub = lane >> 3, rr = lane & 7;
    int row = m0 + ((sub & 1) << 3) + rr;
    int ch  = chb + (sub >> 1);
    int sw  = (ch & 8) | ((ch ^ (row & 7)) & 7);
    return base + row * 256 + sw * 16;
}
__device__ __forceinline__ uint32_t t256_b(uint32_t base, int n0, int chb, int lane) {
    int sub = lane >> 3, rr = lane & 7;
    int row = n0 + ((sub >> 1) << 3) + rr;
    int ch  = chb + (sub & 1);
    int sw  = (ch & 8) | ((ch ^ (row & 7)) & 7);
    return base + row * 256 + sw * 16;
}

__global__ __launch_bounds__(NT, 1)
void spatial_attn_kernel(const float* __restrict__ x,
                         const float* __restrict__ bq,
                         const float* __restrict__ bk,
                         const float* __restrict__ bv,
                         const float* __restrict__ bo,
                         float* __restrict__ out)
{
    extern __shared__ float sm[];
    char* smb = (char*)sm;
    const uint32_t smb0 = smem_u32(sm);
    const int t    = threadIdx.x;
    const int lane = t & 31;
    const int qg   = t >> 5;
    const size_t gbase = (size_t)blockIdx.x * (TT * CCH);
    const float* xg = x + gbase;
    float* yg = out + gbase;

    // warp MMA tile for QKV / Wo MMAs: 2 m-groups (48 rows) x 8 n-groups (16 cols)
    const int m0w = (qg & 1) * 48;
    const int n0w = (qg >> 1) * 16;

    // ======== phase A0: stage X ONCE as bf16 hi/lo 256B-row tiles ========
    if (t < 384) {
        const int row = t >> 2, g = t & 3;
        const float4* src = (const float4*)xg + row * 32 + g * 8;
#pragma unroll
        for (int ii = 0; ii < 4; ++ii) {
            float4 f0 = src[2 * ii], f1 = src[2 * ii + 1];
            uint4 hh, ll;
            hh.x = pk_bf2(f0.x, f0.y, ll.x); hh.y = pk_bf2(f0.z, f0.w, ll.y);
            hh.z = pk_bf2(f1.x, f1.y, ll.z); hh.w = pk_bf2(f1.z, f1.w, ll.w);
            const int lc = g * 4 + ii;                 // logical 16B chunk 0..15
            const int sw = (lc & 8) | ((lc ^ (row & 7)) & 7);
            *(uint4*)(smb + XH2_B + row * 256 + sw * 16) = hh;
            *(uint4*)(smb + XL2_B + row * 256 + sw * 16) = ll;
        }
    }
    // no standalone sync: merged with first W-slab sync below

    // ======== phase A: QKV via mma.sync bf16 split ========
#pragma unroll 1
    for (int m = 0; m < 3; ++m) {
        float acc[3][2][4];
#pragma unroll
        for (int i = 0; i < 3; ++i)
#pragma unroll
            for (int j = 0; j < 2; ++j)
#pragma unroll
                for (int c = 0; c < 4; ++c) acc[i][j][c] = 0.f;

#pragma unroll 1
        for (int kh = 0; kh < 2; ++kh) {
            // stage W slab (m, kh): 128 rows x 128B hi/lo, swizzled (validated pattern)
            {
                const int n = t >> 2;
                const int cb = (t & 3) * 2;
#pragma unroll
                for (int q = 0; q < 2; ++q) {
                    const int cl = cb + q;
                    const int swc = (cl ^ (n & 7)) & 7;
                    uint4 vh = *(const uint4*)((const char*)g_WH[m] + n * 256 + kh * 128 + cl * 16);
                    uint4 vl = *(const uint4*)((const char*)g_WL[m] + n * 256 + kh * 128 + cl * 16);
                    *(uint4*)(smb + WH_B + n * 128 + swc * 16) = vh;
                    *(uint4*)(smb + WL_B + n * 128 + swc * 16) = vl;
                }
            }
            __syncthreads();

#pragma unroll
            for (int kk = 0; kk < 4; ++kk) {
                const int chb = kh * 8 + kk * 2;   // X tile chunk base
                const int c2  = 2 * kk;            // W slab local chunk base
                uint32_t Ah[3][4], Al[3][4], Bh[4], Bl[4];
#pragma unroll
                for (int i = 0; i < 3; ++i) {
                    LDSM4(Ah[i][0], Ah[i][1], Ah[i][2], Ah[i][3],
                          t256_a(smb0 + XH2_B, m0w + 16 * i, chb, lane));
                    LDSM4(Al[i][0], Al[i][1], Al[i][2], Al[i][3],
                          t256_a(smb0 + XL2_B, m0w + 16 * i, chb, lane));
                }
                LDSM4(Bh[0], Bh[1], Bh[2], Bh[3], b_addr(smb0 + WH_B, n0w, c2, lane));
                LDSM4(Bl[0], Bl[1], Bl[2], Bl[3], b_addr(smb0 + WL_B, n0w, c2, lane));
#pragma unroll
                for (int i = 0; i < 3; ++i)
#pragma unroll
                    for (int j = 0; j < 2; ++j) {
                        MMA16816(acc[i][j], Ah[i], Bh[2 * j], Bh[2 * j + 1]);
                        MMA16816(acc[i][j], Ah[i], Bl[2 * j], Bl[2 * j + 1]);
                        MMA16816(acc[i][j], Al[i], Bh[2 * j], Bh[2 * j + 1]);
                    }
            }
            __syncthreads();   // W slab reusable
        }

        // epilogue: +bias, split to bf16 hi/lo, store into 256B-row swizzled tile
        {
            const float* bias = (m == 0) ? bq : (m == 1) ? bk : bv;
            const uint32_t hB = (m == 0) ? QH_B : (m == 1) ? KH_B : VH_B;
            const uint32_t lB = hB + 24576;
#pragma unroll
            for (int j = 0; j < 2; ++j) {
                const int jc = n0w + 8 * j + 2 * (lane & 3);
                const float2 bb = *(const float2*)(bias + jc);
#pragma unroll
                for (int i = 0; i < 3; ++i) {
                    const int r = m0w + 16 * i + (lane >> 2);
#pragma unroll
                    for (int e = 0; e < 2; ++e) {
                        const int rr = r + 8 * e;
                        float vx = acc[i][j][2 * e + 0] + bb.x;
                        float vy = acc[i][j][2 * e + 1] + bb.y;
                        uint32_t lo; uint32_t hi = pk_bf2(vx, vy, lo);
                        const int chb = jc >> 3;
                        const int ch  = (chb & 8) | ((chb ^ (rr & 7)) & 7);
                        const int off = rr * 256 + ch * 16 + (jc & 7) * 2;
                        *(uint32_t*)(smb + hB + off) = hi;
                        *(uint32_t*)(smb + lB + off) = lo;
                    }
                }
            }
        }
    }
    __syncthreads();   // Q/K/V bf16 tiles ready

    // ======== phase B ========
    const float scale = 0.17677669529663687f;  // 1/sqrt(32)
    float accy[3][2][4];
#pragma unroll
    for (int i = 0; i < 3; ++i)
#pragma unroll
        for (int j = 0; j < 2; ++j)
#pragma unroll
            for (int c = 0; c < 4; ++c) accy[i][j][c] = 0.f;

    // A*V warp tiling (12 warps): 96q x 32d
    const int avm = qg % 6;
    const int avn = qg / 6;
    const int q0m = avm * 16;

#pragma unroll 1
    for (int h = 0; h < NH; ++h) {
        const int hc = h * HDIM;
        const int chH = hc >> 3;

        // ---- S_T = K . Q^T via mma.sync (warps 0-11) ----
        if (qg < 12) {
            const int km0 = (qg & 1) * 48;
            const int q0n = (qg >> 1) * 16;
            float accs[3][2][4];
#pragma unroll
            for (int i = 0; i < 3; ++i)
#pragma unroll
                for (int j = 0; j < 2; ++j)
#pragma unroll
                    for (int c = 0; c < 4; ++c) accs[i][j][c] = 0.f;
#pragma unroll
            for (int kk = 0; kk < 2; ++kk) {
                const int chb = chH + 2 * kk;
                uint32_t Kh[3][4], Kl[3][4], Qh[4], Ql[4];
#pragma unroll
                for (int i = 0; i < 3; ++i) {
                    LDSM4(Kh[i][0], Kh[i][1], Kh[i][2], Kh[i][3],
                          t256_a(smb0 + KH_B, km0 + 16 * i, chb, lane));
                    LDSM4(Kl[i][0], Kl[i][1], Kl[i][2], Kl[i][3],
                          t256_a(smb0 + KL_B, km0 + 16 * i, chb, lane));
                }
                LDSM4(Qh[0], Qh[1], Qh[2], Qh[3], t256_b(smb0 + QH_B, q0n, chb, lane));
                LDSM4(Ql[0], Ql[1], Ql[2], Ql[3], t256_b(smb0 + QL_B, q0n, chb, lane));
#pragma unroll
                for (int i = 0; i < 3; ++i)
#pragma unroll
                    for (int j = 0; j < 2; ++j) {
                        MMA16816(accs[i][j], Kh[i], Qh[2 * j], Qh[2 * j + 1]);
                        MMA16816(accs[i][j], Kh[i], Ql[2 * j], Ql[2 * j + 1]);
                        MMA16816(accs[i][j], Kl[i], Qh[2 * j], Qh[2 * j + 1]);
                    }
            }
#pragma unroll
            for (int j = 0; j < 2; ++j) {
                const int qc = q0n + 8 * j + 2 * (lane & 3);
#pragma unroll
                for (int i = 0; i < 3; ++i) {
                    const int kr = km0 + 16 * i + (lane >> 2);
                    float2 v0, v1;
                    v0.x = accs[i][j][0] * scale; v0.y = accs[i][j][1] * scale;
                    v1.x = accs[i][j][2] * scale; v1.y = accs[i][j][3] * scale;
                    *(float2*)(sm + OFF_S + kr * LDSS + qc)       = v0;
                    *(float2*)(sm + OFF_S + (kr + 8) * LDSS + qc) = v1;
                }
            }
        }
        __syncthreads();   // (1) S ready

        // ---- softmax over q (axis=-2); write A directly as bf16 hi/lo ----
        {
#pragma unroll
            for (int r = 0; r < ROWS; ++r) {
                const int k = qg * ROWS + r;
                float v0 = sm[OFF_S + k * LDSS + lane];
                float v1 = sm[OFF_S + k * LDSS + lane + 32];
                float v2 = sm[OFF_S + k * LDSS + lane + 64];
                float mx = fmaxf(v0, fmaxf(v1, v2));
#pragma unroll
                for (int o = 16; o; o >>= 1) mx = fmaxf(mx, __shfl_xor_sync(0xffffffffu, mx, o));
                float e0 = __expf(v0 - mx), e1 = __expf(v1 - mx), e2 = __expf(v2 - mx);
                float s = e0 + e1 + e2;
#pragma unroll
                for (int o = 16; o; o >>= 1) s += __shfl_xor_sync(0xffffffffu, s, o);
                const float inv = 1.f / s;
                const float a0 = e0 * inv, a1 = e1 * inv, a2 = e2 * inv;
                {
                    __nv_bfloat16 bh = __float2bfloat16(a0);
                    __nv_bfloat16 bl = __float2bfloat16(a0 - __bfloat162float(bh));
                    const int ch  = ((lane >> 3) ^ (k & 7)) & 7;
                    const int off = k * 128 + ch * 16 + (lane & 7) * 2;
                    *(__nv_bfloat16*)(smb + AH0_B + off) = bh;
                    *(__nv_bfloat16*)(smb + AL0_B + off) = bl;
                }
                {
                    __nv_bfloat16 bh = __float2bfloat16(a1);
                    __nv_bfloat16 bl = __float2bfloat16(a1 - __bfloat162float(bh));
                    const int ch  = (((lane >> 3) + 4) ^ (k & 7)) & 7;
                    const int off = k * 128 + ch * 16 + (lane & 7) * 2;
                    *(__nv_bfloat16*)(smb + AH0_B + off) = bh;
                    *(__nv_bfloat16*)(smb + AL0_B + off) = bl;
                }
                {
                    __nv_bfloat16 bh = __float2bfloat16(a2);
                    __nv_bfloat16 bl = __float2bfloat16(a2 - __bfloat162float(bh));
                    const int ch  = ((lane >> 3) ^ ((k >> 1) & 3)) & 3;
                    const int off = k * 64 + ch * 16 + (lane & 7) * 2;
                    *(__nv_bfloat16*)(smb + AH1_B + off) = bh;
                    *(__nv_bfloat16*)(smb + AL1_B + off) = bl;
                }
            }
        }
        __syncthreads();   // (2) A ready; S region now dead

        // ---- A*V (warps 0-11) + O staging  ||  Wo-slice staging (warps 12-15) ----
        if (qg < 12) {
            float acco[2][4];
#pragma unroll
            for (int j = 0; j < 2; ++j)
#pragma unroll
                for (int c = 0; c < 4; ++c) acco[j][c] = 0.f;
            const int n0 = hc + avn * 16;
#pragma unroll
            for (int ks = 0; ks < 6; ++ks) {
                const int k0 = ks * 16;
                uint32_t Afh[4], Afl[4], Bfh[4], Bfl[4];
                {
                    const int krA = k0 + (lane & 7) + 8 * (lane >> 4);
                    const int qch = ((q0m & 63) >> 3) + ((lane >> 3) & 1);
                    uint32_t aoff, hB, lB;
                    if (q0m < 64) {
                        aoff = (uint32_t)(krA * 128 + (((qch ^ (krA & 7)) & 7) << 4));
                        hB = AH0_B; lB = AL0_B;
                    } else {
                        aoff = (uint32_t)(krA * 64 + (((qch ^ ((krA >> 1) & 3)) & 3) << 4));
                        hB = AH1_B; lB = AL1_B;
                    }
                    LDSM4T(Afh[0], Afh[1], Afh[2], Afh[3], smb0 + hB + aoff);
                    LDSM4T(Afl[0], Afl[1], Afl[2], Afl[3], smb0 + lB + aoff);
                }
                {
                    const int krV = k0 + (lane & 7) + 8 * ((lane >> 3) & 1);
                    const int dch = (n0 >> 3) + (lane >> 4);
                    const int ch  = (dch & 8) | ((dch ^ (krV & 7)) & 7);
                    const uint32_t voff = (uint32_t)(krV * 256 + ch * 16);
                    LDSM4T(Bfh[0], Bfh[1], Bfh[2], Bfh[3], smb0 + VH_B + voff);
                    LDSM4T(Bfl[0], Bfl[1], Bfl[2], Bfl[3], smb0 + VL_B + voff);
                }
#pragma unroll
                for (int j = 0; j < 2; ++j) {
                    MMA16816(acco[j], Afh, Bfh[2 * j], Bfh[2 * j + 1]);
                    MMA16816(acco[j], Afh, Bfl[2 * j], Bfl[2 * j + 1]);
                    MMA16816(acco[j], Afl, Bfh[2 * j], Bfh[2 * j + 1]);
                }
            }
            // stage O frags (bf16 hi/lo, 64B rows) into dead S region
#pragma unroll
            for (int j = 0; j < 2; ++j) {
                const int dl = avn * 16 + 8 * j + 2 * (lane & 3);
#pragma unroll
                for (int e = 0; e < 2; ++e) {
                    const int q = q0m + (lane >> 2) + 8 * e;
                    uint32_t lo; uint32_t hi = pk_bf2(acco[j][2 * e], acco[j][2 * e + 1], lo);
                    const int ch  = ((dl >> 3) ^ ((q >> 1) & 3)) & 3;
                    const int off = q * 64 + ch * 16 + (dl & 7) * 2;
                    *(uint32_t*)(smb + OH_B + off) = hi;
                    *(uint32_t*)(smb + OL_B + off) = lo;
                }
            }
        } else {
            // warps 12-15 (idle in A*V): stage Wo head-slice into dead S region
            const int n = t & 127;
#pragma unroll
            for (int ch = 0; ch < 4; ++ch) {
                const int swc = (ch ^ ((n >> 1) & 3)) & 3;
                uint4 vh = *(const uint4*)((const char*)g_WH[3] + n * 256 + hc * 2 + ch * 16);
                uint4 vl = *(const uint4*)((const char*)g_WL[3] + n * 256 + hc * 2 + ch * 16);
                *(uint4*)(smb + WOH_B + n * 64 + swc * 16) = vh;
                *(uint4*)(smb + WOL_B + n * 64 + swc * 16) = vl;
            }
        }
        __syncthreads();   // (3) O + Wo slice ready

        // ---- y += O_h @ Wo_h^T via mma.sync (all 16 warps; validated) ----
        {
#pragma unroll
            for (int kk = 0; kk < 2; ++kk) {
                const int c2 = 2 * kk;
                uint32_t Ah2[3][4], Al2[3][4], Bh2[4], Bl2[4];
#pragma unroll
                for (int i = 0; i < 3; ++i) {
                    LDSM4(Ah2[i][0], Ah2[i][1], Ah2[i][2], Ah2[i][3],
                          a64_addr(smb0 + OH_B, m0w + 16 * i, c2, lane));
                    LDSM4(Al2[i][0], Al2[i][1], Al2[i][2], Al2[i][3],
                          a64_addr(smb0 + OL_B, m0w + 16 * i, c2, lane));
                }
                LDSM4(Bh2[0], Bh2[1], Bh2[2], Bh2[3], b64_addr(smb0 + WOH_B, n0w, c2, lane));
                LDSM4(Bl2[0], Bl2[1], Bl2[2], Bl2[3], b64_addr(smb0 + WOL_B, n0w, c2, lane));
#pragma unroll
                for (int i = 0; i < 3; ++i)
#pragma unroll
                    for (int j = 0; j < 2; ++j) {
                        MMA16816(accy[i][j], Ah2[i], Bh2[2 * j], Bh2[2 * j + 1]);
                        MMA16816(accy[i][j], Ah2[i], Bl2[2 * j], Bl2[2 * j + 1]);
                        MMA16816(accy[i][j], Al2[i], Bh2[2 * j], Bh2[2 * j + 1]);
                    }
            }
        }
        __syncthreads();   // (4) O/WO region reusable as next head's S
    }

    // ---- epilogue: y = accy fragments + bo -> global ----
    {
#pragma unroll
        for (int j = 0; j < 2; ++j) {
            const int jc = n0w + 8 * j + 2 * (lane & 3);
            const float2 bb = *(const float2*)(bo + jc);
#pragma unroll
            for (int i = 0; i < 3; ++i) {
                const int r = m0w + 16 * i + (lane >> 2);
                float2 v0, v1;
                v0.x = accy[i][j][0] + bb.x; v0.y = accy[i][j][1] + bb.y;
                v1.x = accy[i][j][2] + bb.x; v1.y = accy[i][j][3] + bb.y;
                *(float2*)(yg + r * CCH + jc)       = v0;
                *(float2*)(yg + (r + 8) * CCH + jc) = v1;
            }
        }
    }
}

extern "C" void kernel_launch(void* const* d_in, const int* in_sizes, int n_in,
                              void* d_out, int out_size)
{
    const float* x  = (const float*)d_in[0];
    const float* Wq = (const float*)d_in[1];
    const float* bq = (const float*)d_in[2];
    const float* Wk = (const float*)d_in[3];
    const float* bk = (const float*)d_in[4];
    const float* Wv = (const float*)d_in[5];
    const float* bv = (const float*)d_in[6];
    const float* Wo = (const float*)d_in[7];
    const float* bo = (const float*)d_in[8];
    float* y = (float*)d_out;

    const int nodes = in_sizes[0] / (TT * CCH);   // 4096

    wsplit_kernel<<<(4 * CCH * CCH + 255) / 256, 256>>>(Wq, Wk, Wv, Wo);

    cudaFuncSetAttribute(spatial_attn_kernel,
                         cudaFuncAttributeMaxDynamicSharedMemorySize, SMEM_BYTES);
    spatial_attn_kernel<<<nodes, NT, SMEM_BYTES>>>(x, bq, bk, bv, bo, y);
}